// round 12
// baseline (speedup 1.0000x reference)
#include <cuda_runtime.h>
#include <math.h>
#include <stddef.h>
#include <stdint.h>

// ---------------------------------------------------------------------------
// Problem constants (fixed by the dataset)
// ---------------------------------------------------------------------------
constexpr int BATCH  = 8;
constexpr int L1 = 1024, L2 = 256, L3 = 64;

// ---------------------------------------------------------------------------
// Scratch (single __device__ buffer; no allocations anywhere)
// ---------------------------------------------------------------------------
constexpr size_t SZ_XZ    = (size_t)BATCH * 512 * 1024;
constexpr size_t SZ_F1    = (size_t)BATCH * 256 * 1024;   // (spacer region)
constexpr size_t SZ_F2    = (size_t)BATCH * 256 * 256;
constexpr size_t SZ_F3    = (size_t)BATCH * 256 * 64;
constexpr size_t SZ_COL2  = (size_t)BATCH * 1024 * 256;
constexpr size_t SZ_COL3  = (size_t)BATCH * 1024 * 64;
constexpr size_t SZ_XD1AB = (size_t)BATCH * 1024 * 80;
constexpr size_t SZ_XD2   = (size_t)BATCH * 256 * 40;
constexpr size_t SZ_XD3   = (size_t)BATCH * 64 * 40;
constexpr size_t SZ_WCAT  = (size_t)80 * 256;
constexpr size_t SZ_Y1    = (size_t)BATCH * 1024 * 256;
constexpr size_t SZ_Y2    = (size_t)BATCH * 256 * 256;
constexpr size_t SZ_Y3    = (size_t)BATCH * 64 * 256;
constexpr size_t SZ_WCOMB = (size_t)512 * 512;
constexpr size_t SZ_BCOMB = 512;

constexpr size_t OFF_XZ    = 0;
constexpr size_t OFF_F1    = OFF_XZ    + SZ_XZ;
constexpr size_t OFF_F2    = OFF_F1    + SZ_F1;
constexpr size_t OFF_F3    = OFF_F2    + SZ_F2;
constexpr size_t OFF_COL2  = OFF_F3    + SZ_F3;
constexpr size_t OFF_COL3  = OFF_COL2  + SZ_COL2;
constexpr size_t OFF_XD1AB = OFF_COL3  + SZ_COL3;
constexpr size_t OFF_XD2   = OFF_XD1AB + SZ_XD1AB;
constexpr size_t OFF_XD3   = OFF_XD2   + SZ_XD2;
constexpr size_t OFF_WCAT  = OFF_XD3   + SZ_XD3;
constexpr size_t OFF_YF1   = OFF_WCAT  + SZ_WCAT;
constexpr size_t OFF_YR1   = OFF_YF1   + SZ_Y1;
constexpr size_t OFF_YF2   = OFF_YR1   + SZ_Y1;
constexpr size_t OFF_YR2   = OFF_YF2   + SZ_Y2;
constexpr size_t OFF_YF3   = OFF_YR2   + SZ_Y2;
constexpr size_t OFF_YR3   = OFF_YF3   + SZ_Y3;
constexpr size_t OFF_Y3O   = OFF_YR3   + SZ_Y3;
constexpr size_t OFF_Y2O   = OFF_Y3O   + SZ_Y3;
constexpr size_t OFF_Y1O   = OFF_Y2O   + SZ_Y2;
constexpr size_t OFF_GATED = OFF_Y1O   + SZ_Y1;
constexpr size_t OFF_WCOMB = OFF_GATED + SZ_F1;
constexpr size_t OFF_BCOMB = OFF_WCOMB + SZ_WCOMB;
constexpr size_t SCRATCH_TOTAL = OFF_BCOMB + SZ_BCOMB;

__device__ float g_scratch[SCRATCH_TOTAL];

// ---------------------------------------------------------------------------
// tf32 helpers
// ---------------------------------------------------------------------------
__device__ __forceinline__ float f2tf(float x)
{
    uint32_t r;
    asm("cvt.rna.tf32.f32 %0, %1;" : "=r"(r) : "f"(x));
    return __uint_as_float(r);
}

__device__ __forceinline__ void mma_tf32(float* d, const uint32_t* a,
                                         const uint32_t* b)
{
    asm volatile(
        "mma.sync.aligned.m16n8k8.row.col.f32.tf32.tf32.f32 "
        "{%0,%1,%2,%3}, {%4,%5,%6,%7}, {%8,%9}, {%0,%1,%2,%3};"
        : "+f"(d[0]), "+f"(d[1]), "+f"(d[2]), "+f"(d[3])
        : "r"(a[0]), "r"(a[1]), "r"(a[2]), "r"(a[3]), "r"(b[0]), "r"(b[1]));
}

// ---------------------------------------------------------------------------
// 128x64x16 TF32 tensor-core GEMM, 128 threads (4 warps, warp tile 64x32).
// Doubled M warp-tile vs previous round: 16 MMAs per 12 fragment-load instrs
// per k8-step (was 8 per 10) -> higher tensor-pipe density.
// A stored fragment-major: 16 blocks [s(2)][m16(8)] of 160 floats;
//   within block: gp*20 + tig*4 + {a0,a1,a2,a3} (LDS.128 per fragment).
// B: [k(16)][n(64)] padded to 72 (scalar loads, conflict-free).
// Contract: C[m,n] = sum_k A[m,k]*B[k,n] (+bias[m]); A row-major shared
// across batch; B batched via blockIdx.z = batch*ksplit + ks; C strided
// (ldcm, ldcn); ksplit>1 -> atomicAdd into pre-initialized C.
// Requires N % 64 == 0, (K/ksplit) % 16 == 0, K/ksplit >= 32.
// ---------------------------------------------------------------------------
__global__ __launch_bounds__(128)
void tgemm_kernel(const float* __restrict__ A, const float* __restrict__ B,
                  float* __restrict__ C, const float* __restrict__ bias,
                  int M, int N, int K, int lda, int ldb,
                  long long strideB, long long strideC,
                  int ldcm, int ldcn, int ksplit)
{
    __shared__ float As2[2][16 * 160];   // 20 KB
    __shared__ float Bs[2][16][72];      // 9 KB

    const int tid  = threadIdx.x;
    const int lane = tid & 31;
    const int warp = tid >> 5;
    const int wm = warp & 1;          // m warp offset: 64*wm
    const int wn = warp >> 1;         // n warp offset: 32*wn
    const int gp  = lane >> 2;        // groupID 0..7
    const int tig = lane & 3;         // thread-in-group 0..3

    const int batch  = blockIdx.z / ksplit;
    const int ks     = blockIdx.z % ksplit;
    const int kchunk = K / ksplit;
    const int kbeg   = ks * kchunk;
    const int kend   = kbeg + kchunk;
    const int m0 = blockIdx.y * 128;
    const int n0 = blockIdx.x * 64;

    const float* Bp = B + (size_t)batch * (size_t)strideB;
    float* Cp = C + (size_t)batch * (size_t)strideC;

    // global-load assignments: A row = tid (128 rows), 16 k per row
    const int brow = tid >> 3;        // 0..15  (k)
    const int bcol = (tid & 7) * 8;   // 0..56  (n)
    const bool aval = (m0 + tid) < M;
    const float* aptr = A + (size_t)(m0 + tid) * lda;
    const float* bptr = Bp + (size_t)brow * ldb + n0 + bcol;

    // writer fragment-major indices for A
    const int aw_m16 = tid >> 4;          // 0..7
    const int aw_gp  = tid & 7;
    const int aw_rh  = (tid >> 3) & 1;
    const int awoff  = aw_gp * 20 + aw_rh;

    float acc[4][4][4];
#pragma unroll
    for (int mt = 0; mt < 4; mt++)
#pragma unroll
        for (int nt = 0; nt < 4; nt++)
#pragma unroll
            for (int r = 0; r < 4; r++) acc[mt][nt][r] = 0.f;

    float apf[16], bpf[8];

    // ---- prefetch tile 0 ----
    if (aval) {
#pragma unroll
        for (int v = 0; v < 4; v++) {
            float4 a = *reinterpret_cast<const float4*>(aptr + kbeg + v * 4);
            apf[v*4+0]=a.x; apf[v*4+1]=a.y; apf[v*4+2]=a.z; apf[v*4+3]=a.w;
        }
    } else {
#pragma unroll
        for (int i = 0; i < 16; i++) apf[i] = 0.f;
    }
    {
        const float* bp = bptr + (size_t)kbeg * ldb;
        float4 b0 = *reinterpret_cast<const float4*>(bp);
        float4 b1 = *reinterpret_cast<const float4*>(bp + 4);
        bpf[0]=b0.x; bpf[1]=b0.y; bpf[2]=b0.z; bpf[3]=b0.w;
        bpf[4]=b1.x; bpf[5]=b1.y; bpf[6]=b1.z; bpf[7]=b1.w;
    }
#pragma unroll
    for (int i = 0; i < 16; i++) {
        const int s = i >> 3, tg = i & 3, ch = (i >> 2) & 1;
        As2[0][(s * 8 + aw_m16) * 160 + awoff + tg * 4 + ch * 2] = f2tf(apf[i]);
    }
#pragma unroll
    for (int i = 0; i < 8; i++) Bs[0][brow][bcol + i] = f2tf(bpf[i]);
    __syncthreads();

    int cur = 0;
    for (int k0 = kbeg + 16; k0 < kend; k0 += 16) {
        // prefetch next K-tile into registers
        if (aval) {
#pragma unroll
            for (int v = 0; v < 4; v++) {
                float4 a = *reinterpret_cast<const float4*>(aptr + k0 + v * 4);
                apf[v*4+0]=a.x; apf[v*4+1]=a.y; apf[v*4+2]=a.z; apf[v*4+3]=a.w;
            }
        }
        {
            const float* bp = bptr + (size_t)k0 * ldb;
            float4 b0 = *reinterpret_cast<const float4*>(bp);
            float4 b1 = *reinterpret_cast<const float4*>(bp + 4);
            bpf[0]=b0.x; bpf[1]=b0.y; bpf[2]=b0.z; bpf[3]=b0.w;
            bpf[4]=b1.x; bpf[5]=b1.y; bpf[6]=b1.z; bpf[7]=b1.w;
        }

        // ---- mma over current buffer: 2 k8-steps, 16 MMA each ----
#pragma unroll
        for (int s = 0; s < 2; s++) {
            uint32_t af[4][4];
#pragma unroll
            for (int mt = 0; mt < 4; mt++) {
                const int aoff = (s * 8 + wm * 4 + mt) * 160 + gp * 20 + tig * 4;
                const float4 fa = *reinterpret_cast<const float4*>(&As2[cur][aoff]);
                af[mt][0] = __float_as_uint(fa.x);
                af[mt][1] = __float_as_uint(fa.y);
                af[mt][2] = __float_as_uint(fa.z);
                af[mt][3] = __float_as_uint(fa.w);
            }
            uint32_t bf[4][2];
#pragma unroll
            for (int nt = 0; nt < 4; nt++) {
                const int nb = wn * 32 + nt * 8;
                bf[nt][0] = __float_as_uint(Bs[cur][s*8 + tig    ][nb + gp]);
                bf[nt][1] = __float_as_uint(Bs[cur][s*8 + tig + 4][nb + gp]);
            }
#pragma unroll
            for (int mt = 0; mt < 4; mt++)
#pragma unroll
                for (int nt = 0; nt < 4; nt++)
                    mma_tf32(acc[mt][nt], af[mt], bf[nt]);
        }

        // store prefetched tile into the other buffer
        const int nxt = cur ^ 1;
#pragma unroll
        for (int i = 0; i < 16; i++) {
            const int s = i >> 3, tg = i & 3, ch = (i >> 2) & 1;
            As2[nxt][(s * 8 + aw_m16) * 160 + awoff + tg * 4 + ch * 2] = f2tf(apf[i]);
        }
#pragma unroll
        for (int i = 0; i < 8; i++) Bs[nxt][brow][bcol + i] = f2tf(bpf[i]);
        __syncthreads();
        cur = nxt;
    }

    // ---- final tile ----
#pragma unroll
    for (int s = 0; s < 2; s++) {
        uint32_t af[4][4];
#pragma unroll
        for (int mt = 0; mt < 4; mt++) {
            const int aoff = (s * 8 + wm * 4 + mt) * 160 + gp * 20 + tig * 4;
            const float4 fa = *reinterpret_cast<const float4*>(&As2[cur][aoff]);
            af[mt][0] = __float_as_uint(fa.x);
            af[mt][1] = __float_as_uint(fa.y);
            af[mt][2] = __float_as_uint(fa.z);
            af[mt][3] = __float_as_uint(fa.w);
        }
        uint32_t bf[4][2];
#pragma unroll
        for (int nt = 0; nt < 4; nt++) {
            const int nb = wn * 32 + nt * 8;
            bf[nt][0] = __float_as_uint(Bs[cur][s*8 + tig    ][nb + gp]);
            bf[nt][1] = __float_as_uint(Bs[cur][s*8 + tig + 4][nb + gp]);
        }
#pragma unroll
        for (int mt = 0; mt < 4; mt++)
#pragma unroll
            for (int nt = 0; nt < 4; nt++)
                mma_tf32(acc[mt][nt], af[mt], bf[nt]);
    }

    // ---- epilogue ----
#pragma unroll
    for (int mt = 0; mt < 4; mt++) {
        const int r0 = m0 + wm * 64 + mt * 16 + gp;
        const int r1 = r0 + 8;
#pragma unroll
        for (int nt = 0; nt < 4; nt++) {
            const int col = n0 + wn * 32 + nt * 8 + 2 * tig;
            if (ksplit == 1) {
                if (r0 < M) {
                    const float bv = bias ? bias[r0] : 0.f;
                    Cp[(size_t)r0 * ldcm + (size_t)col * ldcn]       = acc[mt][nt][0] + bv;
                    Cp[(size_t)r0 * ldcm + (size_t)(col + 1) * ldcn] = acc[mt][nt][1] + bv;
                }
                if (r1 < M) {
                    const float bv = bias ? bias[r1] : 0.f;
                    Cp[(size_t)r1 * ldcm + (size_t)col * ldcn]       = acc[mt][nt][2] + bv;
                    Cp[(size_t)r1 * ldcm + (size_t)(col + 1) * ldcn] = acc[mt][nt][3] + bv;
                }
            } else {
                if (r0 < M) {
                    atomicAdd(&Cp[(size_t)r0 * ldcm + (size_t)col * ldcn],       acc[mt][nt][0]);
                    atomicAdd(&Cp[(size_t)r0 * ldcm + (size_t)(col + 1) * ldcn], acc[mt][nt][1]);
                }
                if (r1 < M) {
                    atomicAdd(&Cp[(size_t)r1 * ldcm + (size_t)col * ldcn],       acc[mt][nt][2]);
                    atomicAdd(&Cp[(size_t)r1 * ldcm + (size_t)(col + 1) * ldcn], acc[mt][nt][3]);
                }
            }
        }
    }
}

// ---------------------------------------------------------------------------
// Wcomb rows 0..255 = c1_w(256x256) @ in_w[0:256](256x512), exact fp32, tiled.
// ---------------------------------------------------------------------------
__global__ __launch_bounds__(256)
void wprep_mm(const float* __restrict__ c1_w,
              const float* __restrict__ in_w,
              float* __restrict__ Wcomb)
{
    __shared__ float Asm[32][33];
    __shared__ float Bsm[32][33];
    const int tx = threadIdx.x;
    const int ty = threadIdx.y;
    const int n0 = blockIdx.x * 32;
    const int m0 = blockIdx.y * 32;

    float acc[4] = {0.f, 0.f, 0.f, 0.f};
    for (int k0 = 0; k0 < 256; k0 += 32) {
#pragma unroll
        for (int i = 0; i < 4; i++)
            Asm[ty + 8 * i][tx] = c1_w[(m0 + ty + 8 * i) * 256 + k0 + tx];
#pragma unroll
        for (int i = 0; i < 4; i++)
            Bsm[ty + 8 * i][tx] = in_w[(k0 + ty + 8 * i) * 512 + n0 + tx];
        __syncthreads();
#pragma unroll
        for (int kk = 0; kk < 32; kk++) {
            const float bv = Bsm[kk][tx];
#pragma unroll
            for (int i = 0; i < 4; i++)
                acc[i] += Asm[ty + 8 * i][kk] * bv;
        }
        __syncthreads();
    }
#pragma unroll
    for (int i = 0; i < 4; i++)
        Wcomb[(m0 + ty + 8 * i) * 512 + n0 + tx] = acc[i];
}

// rows 256..511 copy of in_w, plus combined bias bcomb
__global__ void wprep_rest(const float* __restrict__ in_w,
                           const float* __restrict__ in_b,
                           const float* __restrict__ c1_w,
                           const float* __restrict__ c1_b,
                           float* __restrict__ Wcomb,
                           float* __restrict__ bcomb)
{
    const int idx = blockIdx.x * 256 + threadIdx.x;
    if (idx < 256 * 512)
        Wcomb[256 * 512 + idx] = in_w[256 * 512 + idx];
    if (idx < 256) {
        float a = c1_b[idx];
#pragma unroll 4
        for (int c = 0; c < 256; c++) a += c1_w[idx * 256 + c] * in_b[c];
        bcomb[idx] = a;
    } else if (idx < 512) {
        bcomb[idx] = in_b[idx];
    }
}

// ---------------------------------------------------------------------------
// init for split-K targets: C[b][m][n] = bias ? bias[m] : 0
// ---------------------------------------------------------------------------
__global__ void biasinit_k(float* __restrict__ C, const float* __restrict__ bias,
                           int M, int N, int total)
{
    const int idx = blockIdx.x * blockDim.x + threadIdx.x;
    if (idx >= total) return;
    const int m = (idx / N) % M;
    C[idx] = bias ? bias[m] : 0.f;
}

// concat xw1 (40x256) and xw2 (40x256) -> wcat (80x256)
__global__ void wcat_k(const float* __restrict__ w1, const float* __restrict__ w2,
                       float* __restrict__ dst)
{
    const int idx = blockIdx.x * blockDim.x + threadIdx.x;
    if (idx >= 80 * 256) return;
    dst[idx] = (idx < 40 * 256) ? w1[idx] : w2[idx - 40 * 256];
}

// ---------------------------------------------------------------------------
// im2col for 2x2/stride-2 conv: src [B][*][Hs][Ws] (batch stride sstride)
// -> dst [B][C*4][Ho*Wo]
// ---------------------------------------------------------------------------
__global__ void im2col_k(const float* __restrict__ src, float* __restrict__ dst,
                         int C, int Hs, int Ws, long long sstride)
{
    const int Ho = Hs >> 1, Wo = Ws >> 1;
    const int P = Ho * Wo;
    const int nTot = BATCH * C * 4 * P;
    const int idx = blockIdx.x * blockDim.x + threadIdx.x;
    if (idx >= nTot) return;
    const int n = idx % P;
    const int k = (idx / P) % (C * 4);
    const int b = idx / (P * C * 4);
    const int c = k >> 2;
    const int i = (k >> 1) & 1;
    const int j = k & 1;
    const int h = n / Wo;
    const int w = n % Wo;
    dst[idx] = src[(size_t)b * sstride + ((size_t)c * Hs + 2 * h + i) * Ws + 2 * w + j];
}

// ---------------------------------------------------------------------------
// Selective scan, 4 lanes per (b,d): lane q owns states 4q..4q+3.
// ---------------------------------------------------------------------------
struct ScanCfg {
    const float* x;
    const float* xd;
    float* y;
    const float* dtw;
    const float* dtb;
    const float* Al;
    const float* Dv;
    int L;
    int dir;
    int pitch;
    long long xbstride;
};
struct ScanArgs { ScanCfg c[6]; };

__global__ __launch_bounds__(128)
void scan4_kernel(ScanArgs args)
{
    const ScanCfg cfg = args.c[blockIdx.y];
    const int gid  = blockIdx.x * 128 + threadIdx.x;
    const int q    = gid & 3;
    const int pair = gid >> 2;
    const int b = pair >> 8;
    const int d = pair & 255;
    const int L = cfg.L;
    const int dir = cfg.dir;
    const int pitch = cfg.pitch;

    const float4 dtw0 = *reinterpret_cast<const float4*>(cfg.dtw + d * 8);
    const float4 dtw1 = *reinterpret_cast<const float4*>(cfg.dtw + d * 8 + 4);
    const float dtb_r = cfg.dtb[d];
    const float Dv_r  = cfg.Dv[d];

    float A_r[4];
    bool pwl = true;
#pragma unroll
    for (int j = 0; j < 4; j++) {
        const int n = q * 4 + j;
        A_r[j] = -expf(cfg.Al[d * 16 + n]);
        pwl = pwl && (fabsf(A_r[j] + (float)(n + 1)) <= 1e-4f * (float)(n + 1));
    }
    const bool pw = __all_sync(0xffffffffu, pwl);

    const float* xrow = cfg.x + (size_t)b * (size_t)cfg.xbstride + (size_t)d * L;
    const float* xdb  = cfg.xd + (size_t)b * L * pitch;
    float* yb = cfg.y + (size_t)b * L * 256 + d;

    float h0 = 0.f, h1 = 0.f, h2 = 0.f, h3 = 0.f;

    int l = dir ? (L - 1) : 0;
    const int step = dir ? -1 : 1;

    const float* qp = xdb + (size_t)l * pitch;
    float4 cd0 = *reinterpret_cast<const float4*>(qp);
    float4 cd1 = *reinterpret_cast<const float4*>(qp + 4);
    float4 cB  = *reinterpret_cast<const float4*>(qp + 8 + q * 4);
    float4 cC  = *reinterpret_cast<const float4*>(qp + 24 + q * 4);
    float  cxv = xrow[l];

    for (int t = 0; t < L; t++) {
        const float4 d0 = cd0, d1 = cd1, Bq = cB, Cq = cC;
        const float xv = cxv;
        const int lw = l;
        l += step;
        if (t + 1 < L) {
            const float* np = xdb + (size_t)l * pitch;
            cd0 = *reinterpret_cast<const float4*>(np);
            cd1 = *reinterpret_cast<const float4*>(np + 4);
            cB  = *reinterpret_cast<const float4*>(np + 8 + q * 4);
            cC  = *reinterpret_cast<const float4*>(np + 24 + q * 4);
            cxv = xrow[l];
        }

        float pre = dtb_r
            + d0.x * dtw0.x + d0.y * dtw0.y + d0.z * dtw0.z + d0.w * dtw0.w
            + d1.x * dtw1.x + d1.y * dtw1.y + d1.z * dtw1.z + d1.w * dtw1.w;
        const float delta = (pre > 20.f) ? pre : log1pf(__expf(pre));
        const float dx = delta * xv;

        float r0, r1, r2, r3;
        if (pw) {
            const float p1 = __expf(-delta);
            const float p2 = p1 * p1, p4 = p2 * p2;
            const float base = (q == 0) ? 1.f
                             : (q == 1) ? p4
                             : (q == 2) ? p4 * p4
                                        : p4 * p4 * p4;
            r0 = base * p1; r1 = r0 * p1; r2 = r1 * p1; r3 = r2 * p1;
        } else {
            r0 = __expf(delta * A_r[0]);
            r1 = __expf(delta * A_r[1]);
            r2 = __expf(delta * A_r[2]);
            r3 = __expf(delta * A_r[3]);
        }

        h0 = h0 * r0 + dx * Bq.x;
        h1 = h1 * r1 + dx * Bq.y;
        h2 = h2 * r2 + dx * Bq.z;
        h3 = h3 * r3 + dx * Bq.w;

        float v = h0 * Cq.x + h1 * Cq.y + h2 * Cq.z + h3 * Cq.w;
        if (q == 0) v += xv * Dv_r;
        v += __shfl_xor_sync(0xffffffffu, v, 1);
        v += __shfl_xor_sync(0xffffffffu, v, 2);
        if (q == 0) yb[(size_t)lw * 256] = v;
    }
}

// ---------------------------------------------------------------------------
// Combine: out[b,l,:] = LN(yf)*gf+bef + LN(yr)*gr+ber + up2(src)
// ---------------------------------------------------------------------------
__device__ __forceinline__ float4 warpReduce4(float4 v)
{
#pragma unroll
    for (int o = 16; o > 0; o >>= 1) {
        v.x += __shfl_xor_sync(0xffffffffu, v.x, o);
        v.y += __shfl_xor_sync(0xffffffffu, v.y, o);
        v.z += __shfl_xor_sync(0xffffffffu, v.z, o);
        v.w += __shfl_xor_sync(0xffffffffu, v.w, o);
    }
    return v;
}

__global__ __launch_bounds__(256)
void combine_kernel(const float* __restrict__ yf, const float* __restrict__ yr,
                    const float* __restrict__ gf, const float* __restrict__ bef,
                    const float* __restrict__ gr, const float* __restrict__ ber,
                    const float* __restrict__ up, float* __restrict__ out,
                    int L, int wgrid)
{
    __shared__ float4 red[8];
    const int bl = blockIdx.x;
    const int d  = threadIdx.x;
    const size_t base = (size_t)bl * 256;

    const float vf = yf[base + d];
    const float vr = yr[base + d];

    float4 s = warpReduce4(make_float4(vf, vf * vf, vr, vr * vr));
    const int warp = threadIdx.x >> 5;
    const int lane = threadIdx.x & 31;
    if (lane == 0) red[warp] = s;
    __syncthreads();
    if (warp == 0) {
        float4 t = (lane < 8) ? red[lane] : make_float4(0.f, 0.f, 0.f, 0.f);
#pragma unroll
        for (int o = 4; o > 0; o >>= 1) {
            t.x += __shfl_xor_sync(0xffffffffu, t.x, o);
            t.y += __shfl_xor_sync(0xffffffffu, t.y, o);
            t.z += __shfl_xor_sync(0xffffffffu, t.z, o);
            t.w += __shfl_xor_sync(0xffffffffu, t.w, o);
        }
        if (lane == 0) red[0] = t;
    }
    __syncthreads();
    const float4 tot = red[0];

    const float inv = 1.f / 256.f;
    const float muf = tot.x * inv;
    const float varf = tot.y * inv - muf * muf;
    const float mur = tot.z * inv;
    const float varr = tot.w * inv - mur * mur;

    const float of = (vf - muf) * rsqrtf(varf + 1e-5f) * gf[d] + bef[d];
    const float orr = (vr - mur) * rsqrtf(varr + 1e-5f) * gr[d] + ber[d];

    float u = 0.f;
    if (up) {
        const int b = bl / L, l = bl % L;
        const int hh = l / wgrid, ww = l % wgrid;
        const int lsrc = (hh >> 1) * (wgrid >> 1) + (ww >> 1);
        u = up[((size_t)b * (L >> 2) + lsrc) * 256 + d];
    }
    out[base + d] = of + orr + u;
}

// ---------------------------------------------------------------------------
// Gate: gated[b][c][p] = y1o[b][p][c] * silu(xz[b][256+c][p])
// ---------------------------------------------------------------------------
__global__ __launch_bounds__(256)
void gate_kernel(const float* __restrict__ y1o, const float* __restrict__ xz,
                 float* __restrict__ gated)
{
    __shared__ float tile[32][33];
    const int b = blockIdx.z;
    const int p0 = blockIdx.x * 32;
    const int c0 = blockIdx.y * 32;
    const int tx = threadIdx.x;
    const int ty = threadIdx.y;

#pragma unroll
    for (int k = 0; k < 4; k++) {
        const int p = p0 + ty + k * 8;
        tile[ty + k * 8][tx] = y1o[((size_t)b * 1024 + p) * 256 + c0 + tx];
    }
    __syncthreads();
#pragma unroll
    for (int k = 0; k < 4; k++) {
        const int c = c0 + ty + k * 8;
        const int p = p0 + tx;
        const float z = xz[((size_t)b * 512 + 256 + c) * 1024 + p];
        const float sz = z / (1.f + __expf(-z));
        gated[((size_t)b * 256 + c) * 1024 + p] = tile[tx][ty + k * 8] * sz;
    }
}

// ---------------------------------------------------------------------------
// Launcher
// ---------------------------------------------------------------------------
extern "C" void kernel_launch(void* const* d_in, const int* in_sizes, int n_in,
                              void* d_out, int out_size)
{
    const float* input_f = (const float*)d_in[0];
    const float* in_w    = (const float*)d_in[1];
    const float* in_b    = (const float*)d_in[2];
    const float* c1_w    = (const float*)d_in[3];
    const float* c1_b    = (const float*)d_in[4];
    const float* c2_w    = (const float*)d_in[5];
    const float* c2_b    = (const float*)d_in[6];
    const float* c3_w    = (const float*)d_in[7];
    const float* c3_b    = (const float*)d_in[8];
    const float* out_w   = (const float*)d_in[9];
    const float* out_b   = (const float*)d_in[10];
    const float* xw1  = (const float*)d_in[11];
    const float* dtw1 = (const float*)d_in[12];
    const float* dtb1 = (const float*)d_in[13];
    const float* Al1  = (const float*)d_in[14];
    const float* Dv1  = (const float*)d_in[15];
    const float* g1   = (const float*)d_in[16];
    const float* be1  = (const float*)d_in[17];
    const float* xw2  = (const float*)d_in[18];
    const float* dtw2 = (const float*)d_in[19];
    const float* dtb2 = (const float*)d_in[20];
    const float* Al2  = (const float*)d_in[21];
    const float* Dv2  = (const float*)d_in[22];
    const float* g2   = (const float*)d_in[23];
    const float* be2  = (const float*)d_in[24];
    const float* xw3  = (const float*)d_in[25];
    const float* dtw3 = (const float*)d_in[26];
    const float* dtb3 = (const float*)d_in[27];
    const float* Al3  = (const float*)d_in[28];
    const float* Dv3  = (const float*)d_in[29];
    const float* g3   = (const float*)d_in[30];
    const float* be3  = (const float*)d_in[31];
    (void)in_sizes; (void)n_in; (void)out_size;

    float* scratch = nullptr;
    cudaGetSymbolAddress((void**)&scratch, g_scratch);

    float* xz    = scratch + OFF_XZ;      // rows 0..255 = f1, 256..511 = z
    float* f2    = scratch + OFF_F2;
    float* f3    = scratch + OFF_F3;
    float* col2  = scratch + OFF_COL2;
    float* col3  = scratch + OFF_COL3;
    float* xd1ab = scratch + OFF_XD1AB;
    float* xd2   = scratch + OFF_XD2;
    float* xd3   = scratch + OFF_XD3;
    float* wcat  = scratch + OFF_WCAT;
    float* yf1   = scratch + OFF_YF1;
    float* yr1   = scratch + OFF_YR1;
    float* yf2   = scratch + OFF_YF2;
    float* yr2   = scratch + OFF_YR2;
    float* yf3   = scratch + OFF_YF3;
    float* yr3   = scratch + OFF_YR3;
    float* y3o   = scratch + OFF_Y3O;
    float* y2o   = scratch + OFF_Y2O;
    float* y1o   = scratch + OFF_Y1O;
    float* gated = scratch + OFF_GATED;
    float* Wcomb = scratch + OFF_WCOMB;
    float* bcomb = scratch + OFF_BCOMB;
    float* outp  = (float*)d_out;

    // 0) fold c1 into in-proj (exact fp32, tiled) + xd weight concat
    wprep_mm<<<dim3(16, 8), dim3(32, 8)>>>(c1_w, in_w, Wcomb);
    wprep_rest<<<512, 256>>>(in_w, in_b, c1_w, c1_b, Wcomb, bcomb);
    wcat_k<<<(80 * 256 + 255) / 256, 256>>>(xw1, xw2, wcat);

    // 1) fused in-proj + c1: [f1; z] = Wcomb @ input + bcomb  (M=512,K=512)
    tgemm_kernel<<<dim3(16, 4, BATCH), 128>>>(Wcomb, input_f, xz, bcomb,
        512, 1024, 512, 512, 1024, 512LL * 1024, 512LL * 1024, 1024, 1, 1);

    // 2) f2 = conv2s2(f1): im2col + split-K(4) GEMM (f1 inside xz)
    im2col_k<<<(BATCH * 256 * 4 * 256 + 255) / 256, 256>>>(xz, col2, 256, 32, 32,
                                                           512LL * 1024);
    biasinit_k<<<(BATCH * 256 * 256 + 255) / 256, 256>>>(f2, c2_b, 256, 256,
                                                         BATCH * 256 * 256);
    tgemm_kernel<<<dim3(4, 2, BATCH * 4), 128>>>(c2_w, col2, f2, nullptr,
        256, 256, 1024, 1024, 256, 1024LL * 256, 256LL * 256, 256, 1, 4);

    // 3) f3 = conv2s2(f2): split-K(8)
    im2col_k<<<(BATCH * 256 * 4 * 64 + 255) / 256, 256>>>(f2, col3, 256, 16, 16,
                                                          256LL * 256);
    biasinit_k<<<(BATCH * 256 * 64 + 255) / 256, 256>>>(f3, c3_b, 256, 64,
                                                        BATCH * 256 * 64);
    tgemm_kernel<<<dim3(1, 2, BATCH * 8), 128>>>(c3_w, col3, f3, nullptr,
        256, 64, 1024, 1024, 64, 1024LL * 64, 256LL * 64, 64, 1, 8);

    // 4) xd projections
    tgemm_kernel<<<dim3(16, 1, BATCH), 128>>>(wcat, xz, xd1ab, nullptr,
        80, 1024, 256, 256, 1024, 512LL * 1024, 1024LL * 80, 1, 80, 1);
    biasinit_k<<<(BATCH * 256 * 40 + 255) / 256, 256>>>(xd2, nullptr, 40, 1,
                                                        BATCH * 256 * 40);
    tgemm_kernel<<<dim3(4, 1, BATCH * 4), 128>>>(xw2, f2, xd2, nullptr,
        40, 256, 256, 256, 256, 256LL * 256, 256LL * 40, 1, 40, 4);
    biasinit_k<<<(BATCH * 64 * 40 + 255) / 256, 256>>>(xd3, nullptr, 40, 1,
                                                       BATCH * 64 * 40);
    tgemm_kernel<<<dim3(1, 1, BATCH * 4), 128>>>(xw3, f3, xd3, nullptr,
        40, 64, 256, 256, 64, 256LL * 64, 64LL * 40, 1, 40, 4);

    // 5) all six selective scans in one launch (4 lanes per (b,d))
    ScanArgs sa;
    sa.c[0] = {xz, xd1ab,      yf1, dtw1, dtb1, Al1, Dv1, L1, 0, 80, 512LL * 1024};
    sa.c[1] = {xz, xd1ab + 40, yr1, dtw2, dtb2, Al2, Dv2, L1, 1, 80, 512LL * 1024};
    sa.c[2] = {f2, xd2,        yf2, dtw2, dtb2, Al2, Dv2, L2, 0, 40, 256LL * 256};
    sa.c[3] = {f2, xd2,        yr2, dtw2, dtb2, Al2, Dv2, L2, 1, 40, 256LL * 256};
    sa.c[4] = {f3, xd3,        yf3, dtw3, dtb3, Al3, Dv3, L3, 0, 40, 256LL * 64};
    sa.c[5] = {f3, xd3,        yr3, dtw3, dtb3, Al3, Dv3, L3, 1, 40, 256LL * 64};
    scan4_kernel<<<dim3(64, 6), 128>>>(sa);

    // 6) combine (LayerNorm per direction + sum + upsample-add), bottom-up
    combine_kernel<<<BATCH * L3, 256>>>(yf3, yr3, g3, be3, g3, be3,
                                        (const float*)nullptr, y3o, L3, 8);
    combine_kernel<<<BATCH * L2, 256>>>(yf2, yr2, g2, be2, g2, be2,
                                        y3o, y2o, L2, 16);
    combine_kernel<<<BATCH * L1, 256>>>(yf1, yr1, g1, be1, g2, be2,
                                        y2o, y1o, L1, 32);

    // 7) gate with silu(z) + transpose to [b][c][p]
    gate_kernel<<<dim3(32, 8, BATCH), dim3(32, 8)>>>(y1o, xz, gated);

    // 8) out-projection straight into d_out: M=512,N=1024,K=256
    tgemm_kernel<<<dim3(16, 4, BATCH), 128>>>(out_w, gated, outp, out_b,
        512, 1024, 256, 256, 1024, 256LL * 1024, 512LL * 1024, 1024, 1, 1);
}

// round 14
// speedup vs baseline: 1.0630x; 1.0630x over previous
#include <cuda_runtime.h>
#include <math.h>
#include <stddef.h>
#include <stdint.h>

// ---------------------------------------------------------------------------
// Problem constants (fixed by the dataset)
// ---------------------------------------------------------------------------
constexpr int BATCH  = 8;
constexpr int L1 = 1024, L2 = 256, L3 = 64;

// ---------------------------------------------------------------------------
// Scratch (single __device__ buffer; no allocations anywhere)
// ---------------------------------------------------------------------------
constexpr size_t SZ_XZ    = (size_t)BATCH * 512 * 1024;
constexpr size_t SZ_F1    = (size_t)BATCH * 256 * 1024;   // (spacer region)
constexpr size_t SZ_F2    = (size_t)BATCH * 256 * 256;
constexpr size_t SZ_F3    = (size_t)BATCH * 256 * 64;
constexpr size_t SZ_COL2  = (size_t)BATCH * 1024 * 256;
constexpr size_t SZ_COL3  = (size_t)BATCH * 1024 * 64;
constexpr size_t SZ_XD1AB = (size_t)BATCH * 1024 * 80;
constexpr size_t SZ_XD2   = (size_t)BATCH * 256 * 40;
constexpr size_t SZ_XD3   = (size_t)BATCH * 64 * 40;
constexpr size_t SZ_WCAT  = (size_t)80 * 256;
constexpr size_t SZ_Y1    = (size_t)BATCH * 1024 * 256;
constexpr size_t SZ_Y2    = (size_t)BATCH * 256 * 256;
constexpr size_t SZ_Y3    = (size_t)BATCH * 64 * 256;
constexpr size_t SZ_WCOMB = (size_t)512 * 512;
constexpr size_t SZ_BCOMB = 512;

constexpr size_t OFF_XZ    = 0;
constexpr size_t OFF_F1    = OFF_XZ    + SZ_XZ;
constexpr size_t OFF_F2    = OFF_F1    + SZ_F1;
constexpr size_t OFF_F3    = OFF_F2    + SZ_F2;
constexpr size_t OFF_COL2  = OFF_F3    + SZ_F3;
constexpr size_t OFF_COL3  = OFF_COL2  + SZ_COL2;
constexpr size_t OFF_XD1AB = OFF_COL3  + SZ_COL3;
constexpr size_t OFF_XD2   = OFF_XD1AB + SZ_XD1AB;
constexpr size_t OFF_XD3   = OFF_XD2   + SZ_XD2;
constexpr size_t OFF_WCAT  = OFF_XD3   + SZ_XD3;
constexpr size_t OFF_YF1   = OFF_WCAT  + SZ_WCAT;
constexpr size_t OFF_YR1   = OFF_YF1   + SZ_Y1;
constexpr size_t OFF_YF2   = OFF_YR1   + SZ_Y1;
constexpr size_t OFF_YR2   = OFF_YF2   + SZ_Y2;
constexpr size_t OFF_YF3   = OFF_YR2   + SZ_Y2;
constexpr size_t OFF_YR3   = OFF_YF3   + SZ_Y3;
constexpr size_t OFF_Y3O   = OFF_YR3   + SZ_Y3;
constexpr size_t OFF_Y2O   = OFF_Y3O   + SZ_Y3;
constexpr size_t OFF_Y1O   = OFF_Y2O   + SZ_Y2;
constexpr size_t OFF_GATED = OFF_Y1O   + SZ_Y1;
constexpr size_t OFF_WCOMB = OFF_GATED + SZ_F1;
constexpr size_t OFF_BCOMB = OFF_WCOMB + SZ_WCOMB;
constexpr size_t SCRATCH_TOTAL = OFF_BCOMB + SZ_BCOMB;

__device__ float g_scratch[SCRATCH_TOTAL];

// ---------------------------------------------------------------------------
// tf32 helpers
// ---------------------------------------------------------------------------
__device__ __forceinline__ float f2tf(float x)
{
    uint32_t r;
    asm("cvt.rna.tf32.f32 %0, %1;" : "=r"(r) : "f"(x));
    return __uint_as_float(r);
}

__device__ __forceinline__ void mma_tf32(float* d, const uint32_t* a,
                                         const uint32_t* b)
{
    asm volatile(
        "mma.sync.aligned.m16n8k8.row.col.f32.tf32.tf32.f32 "
        "{%0,%1,%2,%3}, {%4,%5,%6,%7}, {%8,%9}, {%0,%1,%2,%3};"
        : "+f"(d[0]), "+f"(d[1]), "+f"(d[2]), "+f"(d[3])
        : "r"(a[0]), "r"(a[1]), "r"(a[2]), "r"(a[3]), "r"(b[0]), "r"(b[1]));
}

// ---------------------------------------------------------------------------
// 64x64x16 TF32 tensor-core GEMM, 128 threads (4 warps, warp tile 32x32),
// double-buffered SMEM with global->register prefetch.
// BOTH operands stored FRAGMENT-MAJOR:
//   A: 8 blocks [s(2)][m16(4)] of 160 floats; frag = LDS.128 at
//      blk*160 + gp*20 + tig*4 (conflict-free).
//   B: 16 blocks [s(2)][n8(8)] of 68 floats; frag = LDS.64 at
//      blk*68 + gp*8 + tig*2 (lane-linear -> conflict-free; writes <=2-way).
// Per k8-step: 2 LDS.128 + 4 LDS.64 feed 8 MMAs (was 10 loads w/ 8-way STS
// conflicts on B).
// Contract: C[m,n] = sum_k A[m,k]*B[k,n] (+bias[m]); A row-major shared
// across batch; B batched via blockIdx.z = batch*ksplit + ks; C strided
// (ldcm, ldcn); ksplit>1 -> atomicAdd into pre-initialized C.
// Requires N % 64 == 0, (K/ksplit) % 16 == 0, K/ksplit >= 32.
// ---------------------------------------------------------------------------
__global__ __launch_bounds__(128)
void tgemm_kernel(const float* __restrict__ A, const float* __restrict__ B,
                  float* __restrict__ C, const float* __restrict__ bias,
                  int M, int N, int K, int lda, int ldb,
                  long long strideB, long long strideC,
                  int ldcm, int ldcn, int ksplit)
{
    __shared__ float As2[2][8 * 160];    // 10 KB
    __shared__ float Bs2[2][16 * 68];    // 8.7 KB

    const int tid  = threadIdx.x;
    const int lane = tid & 31;
    const int warp = tid >> 5;
    const int wm = warp & 1;          // m warp offset: 32*wm
    const int wn = warp >> 1;         // n warp offset: 32*wn
    const int gp  = lane >> 2;        // groupID 0..7
    const int tig = lane & 3;         // thread-in-group 0..3

    const int batch  = blockIdx.z / ksplit;
    const int ks     = blockIdx.z % ksplit;
    const int kchunk = K / ksplit;
    const int kbeg   = ks * kchunk;
    const int kend   = kbeg + kchunk;
    const int m0 = blockIdx.y * 64;
    const int n0 = blockIdx.x * 64;

    const float* Bp = B + (size_t)batch * (size_t)strideB;
    float* Cp = C + (size_t)batch * (size_t)strideC;

    // global-load assignments
    const int arow = tid >> 1;        // 0..63  (m)
    const int acol = (tid & 1) * 8;   // 0/8    (k)
    const int brow = tid >> 3;        // 0..15  (k)
    const int bcol = (tid & 7) * 8;   // 0..56  (n)
    const bool aval = (m0 + arow) < M;
    const float* aptr = A + (size_t)(m0 + arow) * lda + acol;
    const float* bptr = Bp + (size_t)brow * ldb + n0 + bcol;

    // A writer fragment-major base
    const int aw_s   = (tid & 1);
    const int aw_m16 = arow >> 4;
    const int aw_gp  = arow & 7;
    const int aw_rh  = (arow >> 3) & 1;
    const int awbase = (aw_s * 4 + aw_m16) * 160 + aw_gp * 20 + aw_rh;

    // B writer fragment-major base: n8 = tid&7 (const), gp_w = i
    const int bw_s   = brow >> 3;
    const int bw_kq  = brow & 7;
    const int bwbase = (bw_s * 8 + (tid & 7)) * 68 + (bw_kq & 3) * 2 + (bw_kq >> 2);

    float acc[2][4][4];
#pragma unroll
    for (int mt = 0; mt < 2; mt++)
#pragma unroll
        for (int nt = 0; nt < 4; nt++)
#pragma unroll
            for (int r = 0; r < 4; r++) acc[mt][nt][r] = 0.f;

    float apf[8], bpf[8];

    // ---- prefetch tile 0 ----
    if (aval) {
        float4 a0 = *reinterpret_cast<const float4*>(aptr + kbeg);
        float4 a1 = *reinterpret_cast<const float4*>(aptr + kbeg + 4);
        apf[0]=a0.x; apf[1]=a0.y; apf[2]=a0.z; apf[3]=a0.w;
        apf[4]=a1.x; apf[5]=a1.y; apf[6]=a1.z; apf[7]=a1.w;
    } else {
#pragma unroll
        for (int i = 0; i < 8; i++) apf[i] = 0.f;
    }
    {
        const float* bp = bptr + (size_t)kbeg * ldb;
        float4 b0 = *reinterpret_cast<const float4*>(bp);
        float4 b1 = *reinterpret_cast<const float4*>(bp + 4);
        bpf[0]=b0.x; bpf[1]=b0.y; bpf[2]=b0.z; bpf[3]=b0.w;
        bpf[4]=b1.x; bpf[5]=b1.y; bpf[6]=b1.z; bpf[7]=b1.w;
    }
#pragma unroll
    for (int i = 0; i < 8; i++)
        As2[0][awbase + (i & 3) * 4 + (i >> 2) * 2] = f2tf(apf[i]);
#pragma unroll
    for (int i = 0; i < 8; i++)
        Bs2[0][bwbase + i * 8] = f2tf(bpf[i]);
    __syncthreads();

    int cur = 0;
    for (int k0 = kbeg + 16; k0 < kend; k0 += 16) {
        // prefetch next K-tile into registers
        if (aval) {
            float4 a0 = *reinterpret_cast<const float4*>(aptr + k0);
            float4 a1 = *reinterpret_cast<const float4*>(aptr + k0 + 4);
            apf[0]=a0.x; apf[1]=a0.y; apf[2]=a0.z; apf[3]=a0.w;
            apf[4]=a1.x; apf[5]=a1.y; apf[6]=a1.z; apf[7]=a1.w;
        }
        {
            const float* bp = bptr + (size_t)k0 * ldb;
            float4 b0 = *reinterpret_cast<const float4*>(bp);
            float4 b1 = *reinterpret_cast<const float4*>(bp + 4);
            bpf[0]=b0.x; bpf[1]=b0.y; bpf[2]=b0.z; bpf[3]=b0.w;
            bpf[4]=b1.x; bpf[5]=b1.y; bpf[6]=b1.z; bpf[7]=b1.w;
        }

        // ---- mma over current buffer: 2 k8-steps ----
#pragma unroll
        for (int s = 0; s < 2; s++) {
            uint32_t af[2][4];
#pragma unroll
            for (int mt = 0; mt < 2; mt++) {
                const int aoff = (s * 4 + (wm * 2 + mt)) * 160 + gp * 20 + tig * 4;
                const float4 fa = *reinterpret_cast<const float4*>(&As2[cur][aoff]);
                af[mt][0] = __float_as_uint(fa.x);
                af[mt][1] = __float_as_uint(fa.y);
                af[mt][2] = __float_as_uint(fa.z);
                af[mt][3] = __float_as_uint(fa.w);
            }
            uint32_t bf[4][2];
#pragma unroll
            for (int nt = 0; nt < 4; nt++) {
                const int boff = (s * 8 + wn * 4 + nt) * 68 + gp * 8 + tig * 2;
                const float2 fb = *reinterpret_cast<const float2*>(&Bs2[cur][boff]);
                bf[nt][0] = __float_as_uint(fb.x);
                bf[nt][1] = __float_as_uint(fb.y);
            }
#pragma unroll
            for (int mt = 0; mt < 2; mt++)
#pragma unroll
                for (int nt = 0; nt < 4; nt++)
                    mma_tf32(acc[mt][nt], af[mt], bf[nt]);
        }

        // store prefetched tile into the other buffer
        const int nxt = cur ^ 1;
#pragma unroll
        for (int i = 0; i < 8; i++)
            As2[nxt][awbase + (i & 3) * 4 + (i >> 2) * 2] = f2tf(apf[i]);
#pragma unroll
        for (int i = 0; i < 8; i++)
            Bs2[nxt][bwbase + i * 8] = f2tf(bpf[i]);
        __syncthreads();
        cur = nxt;
    }

    // ---- final tile ----
#pragma unroll
    for (int s = 0; s < 2; s++) {
        uint32_t af[2][4];
#pragma unroll
        for (int mt = 0; mt < 2; mt++) {
            const int aoff = (s * 4 + (wm * 2 + mt)) * 160 + gp * 20 + tig * 4;
            const float4 fa = *reinterpret_cast<const float4*>(&As2[cur][aoff]);
            af[mt][0] = __float_as_uint(fa.x);
            af[mt][1] = __float_as_uint(fa.y);
            af[mt][2] = __float_as_uint(fa.z);
            af[mt][3] = __float_as_uint(fa.w);
        }
        uint32_t bf[4][2];
#pragma unroll
        for (int nt = 0; nt < 4; nt++) {
            const int boff = (s * 8 + wn * 4 + nt) * 68 + gp * 8 + tig * 2;
            const float2 fb = *reinterpret_cast<const float2*>(&Bs2[cur][boff]);
            bf[nt][0] = __float_as_uint(fb.x);
            bf[nt][1] = __float_as_uint(fb.y);
        }
#pragma unroll
        for (int mt = 0; mt < 2; mt++)
#pragma unroll
            for (int nt = 0; nt < 4; nt++)
                mma_tf32(acc[mt][nt], af[mt], bf[nt]);
    }

    // ---- epilogue ----
#pragma unroll
    for (int mt = 0; mt < 2; mt++) {
        const int r0 = m0 + wm * 32 + mt * 16 + gp;
        const int r1 = r0 + 8;
#pragma unroll
        for (int nt = 0; nt < 4; nt++) {
            const int col = n0 + wn * 32 + nt * 8 + 2 * tig;
            if (ksplit == 1) {
                if (r0 < M) {
                    const float bv = bias ? bias[r0] : 0.f;
                    Cp[(size_t)r0 * ldcm + (size_t)col * ldcn]       = acc[mt][nt][0] + bv;
                    Cp[(size_t)r0 * ldcm + (size_t)(col + 1) * ldcn] = acc[mt][nt][1] + bv;
                }
                if (r1 < M) {
                    const float bv = bias ? bias[r1] : 0.f;
                    Cp[(size_t)r1 * ldcm + (size_t)col * ldcn]       = acc[mt][nt][2] + bv;
                    Cp[(size_t)r1 * ldcm + (size_t)(col + 1) * ldcn] = acc[mt][nt][3] + bv;
                }
            } else {
                if (r0 < M) {
                    atomicAdd(&Cp[(size_t)r0 * ldcm + (size_t)col * ldcn],       acc[mt][nt][0]);
                    atomicAdd(&Cp[(size_t)r0 * ldcm + (size_t)(col + 1) * ldcn], acc[mt][nt][1]);
                }
                if (r1 < M) {
                    atomicAdd(&Cp[(size_t)r1 * ldcm + (size_t)col * ldcn],       acc[mt][nt][2]);
                    atomicAdd(&Cp[(size_t)r1 * ldcm + (size_t)(col + 1) * ldcn], acc[mt][nt][3]);
                }
            }
        }
    }
}

// ---------------------------------------------------------------------------
// Wcomb rows 0..255 = c1_w(256x256) @ in_w[0:256](256x512), exact fp32, tiled.
// ---------------------------------------------------------------------------
__global__ __launch_bounds__(256)
void wprep_mm(const float* __restrict__ c1_w,
              const float* __restrict__ in_w,
              float* __restrict__ Wcomb)
{
    __shared__ float Asm[32][33];
    __shared__ float Bsm[32][33];
    const int tx = threadIdx.x;
    const int ty = threadIdx.y;
    const int n0 = blockIdx.x * 32;
    const int m0 = blockIdx.y * 32;

    float acc[4] = {0.f, 0.f, 0.f, 0.f};
    for (int k0 = 0; k0 < 256; k0 += 32) {
#pragma unroll
        for (int i = 0; i < 4; i++)
            Asm[ty + 8 * i][tx] = c1_w[(m0 + ty + 8 * i) * 256 + k0 + tx];
#pragma unroll
        for (int i = 0; i < 4; i++)
            Bsm[ty + 8 * i][tx] = in_w[(k0 + ty + 8 * i) * 512 + n0 + tx];
        __syncthreads();
#pragma unroll
        for (int kk = 0; kk < 32; kk++) {
            const float bv = Bsm[kk][tx];
#pragma unroll
            for (int i = 0; i < 4; i++)
                acc[i] += Asm[ty + 8 * i][kk] * bv;
        }
        __syncthreads();
    }
#pragma unroll
    for (int i = 0; i < 4; i++)
        Wcomb[(m0 + ty + 8 * i) * 512 + n0 + tx] = acc[i];
}

// rows 256..511 copy of in_w, plus combined bias bcomb
__global__ void wprep_rest(const float* __restrict__ in_w,
                           const float* __restrict__ in_b,
                           const float* __restrict__ c1_w,
                           const float* __restrict__ c1_b,
                           float* __restrict__ Wcomb,
                           float* __restrict__ bcomb)
{
    const int idx = blockIdx.x * 256 + threadIdx.x;
    if (idx < 256 * 512)
        Wcomb[256 * 512 + idx] = in_w[256 * 512 + idx];
    if (idx < 256) {
        float a = c1_b[idx];
#pragma unroll 4
        for (int c = 0; c < 256; c++) a += c1_w[idx * 256 + c] * in_b[c];
        bcomb[idx] = a;
    } else if (idx < 512) {
        bcomb[idx] = in_b[idx];
    }
}

// ---------------------------------------------------------------------------
// init for split-K targets: C[b][m][n] = bias ? bias[m] : 0
// ---------------------------------------------------------------------------
__global__ void biasinit_k(float* __restrict__ C, const float* __restrict__ bias,
                           int M, int N, int total)
{
    const int idx = blockIdx.x * blockDim.x + threadIdx.x;
    if (idx >= total) return;
    const int m = (idx / N) % M;
    C[idx] = bias ? bias[m] : 0.f;
}

// concat xw1 (40x256) and xw2 (40x256) -> wcat (80x256)
__global__ void wcat_k(const float* __restrict__ w1, const float* __restrict__ w2,
                       float* __restrict__ dst)
{
    const int idx = blockIdx.x * blockDim.x + threadIdx.x;
    if (idx >= 80 * 256) return;
    dst[idx] = (idx < 40 * 256) ? w1[idx] : w2[idx - 40 * 256];
}

// ---------------------------------------------------------------------------
// im2col for 2x2/stride-2 conv: src [B][*][Hs][Ws] (batch stride sstride)
// -> dst [B][C*4][Ho*Wo]
// ---------------------------------------------------------------------------
__global__ void im2col_k(const float* __restrict__ src, float* __restrict__ dst,
                         int C, int Hs, int Ws, long long sstride)
{
    const int Ho = Hs >> 1, Wo = Ws >> 1;
    const int P = Ho * Wo;
    const int nTot = BATCH * C * 4 * P;
    const int idx = blockIdx.x * blockDim.x + threadIdx.x;
    if (idx >= nTot) return;
    const int n = idx % P;
    const int k = (idx / P) % (C * 4);
    const int b = idx / (P * C * 4);
    const int c = k >> 2;
    const int i = (k >> 1) & 1;
    const int j = k & 1;
    const int h = n / Wo;
    const int w = n % Wo;
    dst[idx] = src[(size_t)b * sstride + ((size_t)c * Hs + 2 * h + i) * Ws + 2 * w + j];
}

// ---------------------------------------------------------------------------
// Selective scan, 4 lanes per (b,d): lane q owns states 4q..4q+3.
// ---------------------------------------------------------------------------
struct ScanCfg {
    const float* x;
    const float* xd;
    float* y;
    const float* dtw;
    const float* dtb;
    const float* Al;
    const float* Dv;
    int L;
    int dir;
    int pitch;
    long long xbstride;
};
struct ScanArgs { ScanCfg c[6]; };

__global__ __launch_bounds__(128)
void scan4_kernel(ScanArgs args)
{
    const ScanCfg cfg = args.c[blockIdx.y];
    const int gid  = blockIdx.x * 128 + threadIdx.x;
    const int q    = gid & 3;
    const int pair = gid >> 2;
    const int b = pair >> 8;
    const int d = pair & 255;
    const int L = cfg.L;
    const int dir = cfg.dir;
    const int pitch = cfg.pitch;

    const float4 dtw0 = *reinterpret_cast<const float4*>(cfg.dtw + d * 8);
    const float4 dtw1 = *reinterpret_cast<const float4*>(cfg.dtw + d * 8 + 4);
    const float dtb_r = cfg.dtb[d];
    const float Dv_r  = cfg.Dv[d];

    float A_r[4];
    bool pwl = true;
#pragma unroll
    for (int j = 0; j < 4; j++) {
        const int n = q * 4 + j;
        A_r[j] = -expf(cfg.Al[d * 16 + n]);
        pwl = pwl && (fabsf(A_r[j] + (float)(n + 1)) <= 1e-4f * (float)(n + 1));
    }
    const bool pw = __all_sync(0xffffffffu, pwl);

    const float* xrow = cfg.x + (size_t)b * (size_t)cfg.xbstride + (size_t)d * L;
    const float* xdb  = cfg.xd + (size_t)b * L * pitch;
    float* yb = cfg.y + (size_t)b * L * 256 + d;

    float h0 = 0.f, h1 = 0.f, h2 = 0.f, h3 = 0.f;

    int l = dir ? (L - 1) : 0;
    const int step = dir ? -1 : 1;

    const float* qp = xdb + (size_t)l * pitch;
    float4 cd0 = *reinterpret_cast<const float4*>(qp);
    float4 cd1 = *reinterpret_cast<const float4*>(qp + 4);
    float4 cB  = *reinterpret_cast<const float4*>(qp + 8 + q * 4);
    float4 cC  = *reinterpret_cast<const float4*>(qp + 24 + q * 4);
    float  cxv = xrow[l];

    for (int t = 0; t < L; t++) {
        const float4 d0 = cd0, d1 = cd1, Bq = cB, Cq = cC;
        const float xv = cxv;
        const int lw = l;
        l += step;
        if (t + 1 < L) {
            const float* np = xdb + (size_t)l * pitch;
            cd0 = *reinterpret_cast<const float4*>(np);
            cd1 = *reinterpret_cast<const float4*>(np + 4);
            cB  = *reinterpret_cast<const float4*>(np + 8 + q * 4);
            cC  = *reinterpret_cast<const float4*>(np + 24 + q * 4);
            cxv = xrow[l];
        }

        float pre = dtb_r
            + d0.x * dtw0.x + d0.y * dtw0.y + d0.z * dtw0.z + d0.w * dtw0.w
            + d1.x * dtw1.x + d1.y * dtw1.y + d1.z * dtw1.z + d1.w * dtw1.w;
        const float delta = (pre > 20.f) ? pre : log1pf(__expf(pre));
        const float dx = delta * xv;

        float r0, r1, r2, r3;
        if (pw) {
            const float p1 = __expf(-delta);
            const float p2 = p1 * p1, p4 = p2 * p2;
            const float base = (q == 0) ? 1.f
                             : (q == 1) ? p4
                             : (q == 2) ? p4 * p4
                                        : p4 * p4 * p4;
            r0 = base * p1; r1 = r0 * p1; r2 = r1 * p1; r3 = r2 * p1;
        } else {
            r0 = __expf(delta * A_r[0]);
            r1 = __expf(delta * A_r[1]);
            r2 = __expf(delta * A_r[2]);
            r3 = __expf(delta * A_r[3]);
        }

        h0 = h0 * r0 + dx * Bq.x;
        h1 = h1 * r1 + dx * Bq.y;
        h2 = h2 * r2 + dx * Bq.z;
        h3 = h3 * r3 + dx * Bq.w;

        float v = h0 * Cq.x + h1 * Cq.y + h2 * Cq.z + h3 * Cq.w;
        if (q == 0) v += xv * Dv_r;
        v += __shfl_xor_sync(0xffffffffu, v, 1);
        v += __shfl_xor_sync(0xffffffffu, v, 2);
        if (q == 0) yb[(size_t)lw * 256] = v;
    }
}

// ---------------------------------------------------------------------------
// Combine: out[b,l,:] = LN(yf)*gf+bef + LN(yr)*gr+ber + up2(src)
// ---------------------------------------------------------------------------
__device__ __forceinline__ float4 warpReduce4(float4 v)
{
#pragma unroll
    for (int o = 16; o > 0; o >>= 1) {
        v.x += __shfl_xor_sync(0xffffffffu, v.x, o);
        v.y += __shfl_xor_sync(0xffffffffu, v.y, o);
        v.z += __shfl_xor_sync(0xffffffffu, v.z, o);
        v.w += __shfl_xor_sync(0xffffffffu, v.w, o);
    }
    return v;
}

__global__ __launch_bounds__(256)
void combine_kernel(const float* __restrict__ yf, const float* __restrict__ yr,
                    const float* __restrict__ gf, const float* __restrict__ bef,
                    const float* __restrict__ gr, const float* __restrict__ ber,
                    const float* __restrict__ up, float* __restrict__ out,
                    int L, int wgrid)
{
    __shared__ float4 red[8];
    const int bl = blockIdx.x;
    const int d  = threadIdx.x;
    const size_t base = (size_t)bl * 256;

    const float vf = yf[base + d];
    const float vr = yr[base + d];

    float4 s = warpReduce4(make_float4(vf, vf * vf, vr, vr * vr));
    const int warp = threadIdx.x >> 5;
    const int lane = threadIdx.x & 31;
    if (lane == 0) red[warp] = s;
    __syncthreads();
    if (warp == 0) {
        float4 t = (lane < 8) ? red[lane] : make_float4(0.f, 0.f, 0.f, 0.f);
#pragma unroll
        for (int o = 4; o > 0; o >>= 1) {
            t.x += __shfl_xor_sync(0xffffffffu, t.x, o);
            t.y += __shfl_xor_sync(0xffffffffu, t.y, o);
            t.z += __shfl_xor_sync(0xffffffffu, t.z, o);
            t.w += __shfl_xor_sync(0xffffffffu, t.w, o);
        }
        if (lane == 0) red[0] = t;
    }
    __syncthreads();
    const float4 tot = red[0];

    const float inv = 1.f / 256.f;
    const float muf = tot.x * inv;
    const float varf = tot.y * inv - muf * muf;
    const float mur = tot.z * inv;
    const float varr = tot.w * inv - mur * mur;

    const float of = (vf - muf) * rsqrtf(varf + 1e-5f) * gf[d] + bef[d];
    const float orr = (vr - mur) * rsqrtf(varr + 1e-5f) * gr[d] + ber[d];

    float u = 0.f;
    if (up) {
        const int b = bl / L, l = bl % L;
        const int hh = l / wgrid, ww = l % wgrid;
        const int lsrc = (hh >> 1) * (wgrid >> 1) + (ww >> 1);
        u = up[((size_t)b * (L >> 2) + lsrc) * 256 + d];
    }
    out[base + d] = of + orr + u;
}

// ---------------------------------------------------------------------------
// Gate: gated[b][c][p] = y1o[b][p][c] * silu(xz[b][256+c][p])
// ---------------------------------------------------------------------------
__global__ __launch_bounds__(256)
void gate_kernel(const float* __restrict__ y1o, const float* __restrict__ xz,
                 float* __restrict__ gated)
{
    __shared__ float tile[32][33];
    const int b = blockIdx.z;
    const int p0 = blockIdx.x * 32;
    const int c0 = blockIdx.y * 32;
    const int tx = threadIdx.x;
    const int ty = threadIdx.y;

#pragma unroll
    for (int k = 0; k < 4; k++) {
        const int p = p0 + ty + k * 8;
        tile[ty + k * 8][tx] = y1o[((size_t)b * 1024 + p) * 256 + c0 + tx];
    }
    __syncthreads();
#pragma unroll
    for (int k = 0; k < 4; k++) {
        const int c = c0 + ty + k * 8;
        const int p = p0 + tx;
        const float z = xz[((size_t)b * 512 + 256 + c) * 1024 + p];
        const float sz = z / (1.f + __expf(-z));
        gated[((size_t)b * 256 + c) * 1024 + p] = tile[tx][ty + k * 8] * sz;
    }
}

// ---------------------------------------------------------------------------
// Launcher
// ---------------------------------------------------------------------------
extern "C" void kernel_launch(void* const* d_in, const int* in_sizes, int n_in,
                              void* d_out, int out_size)
{
    const float* input_f = (const float*)d_in[0];
    const float* in_w    = (const float*)d_in[1];
    const float* in_b    = (const float*)d_in[2];
    const float* c1_w    = (const float*)d_in[3];
    const float* c1_b    = (const float*)d_in[4];
    const float* c2_w    = (const float*)d_in[5];
    const float* c2_b    = (const float*)d_in[6];
    const float* c3_w    = (const float*)d_in[7];
    const float* c3_b    = (const float*)d_in[8];
    const float* out_w   = (const float*)d_in[9];
    const float* out_b   = (const float*)d_in[10];
    const float* xw1  = (const float*)d_in[11];
    const float* dtw1 = (const float*)d_in[12];
    const float* dtb1 = (const float*)d_in[13];
    const float* Al1  = (const float*)d_in[14];
    const float* Dv1  = (const float*)d_in[15];
    const float* g1   = (const float*)d_in[16];
    const float* be1  = (const float*)d_in[17];
    const float* xw2  = (const float*)d_in[18];
    const float* dtw2 = (const float*)d_in[19];
    const float* dtb2 = (const float*)d_in[20];
    const float* Al2  = (const float*)d_in[21];
    const float* Dv2  = (const float*)d_in[22];
    const float* g2   = (const float*)d_in[23];
    const float* be2  = (const float*)d_in[24];
    const float* xw3  = (const float*)d_in[25];
    const float* dtw3 = (const float*)d_in[26];
    const float* dtb3 = (const float*)d_in[27];
    const float* Al3  = (const float*)d_in[28];
    const float* Dv3  = (const float*)d_in[29];
    const float* g3   = (const float*)d_in[30];
    const float* be3  = (const float*)d_in[31];
    (void)in_sizes; (void)n_in; (void)out_size;

    float* scratch = nullptr;
    cudaGetSymbolAddress((void**)&scratch, g_scratch);

    float* xz    = scratch + OFF_XZ;      // rows 0..255 = f1, 256..511 = z
    float* f2    = scratch + OFF_F2;
    float* f3    = scratch + OFF_F3;
    float* col2  = scratch + OFF_COL2;
    float* col3  = scratch + OFF_COL3;
    float* xd1ab = scratch + OFF_XD1AB;
    float* xd2   = scratch + OFF_XD2;
    float* xd3   = scratch + OFF_XD3;
    float* wcat  = scratch + OFF_WCAT;
    float* yf1   = scratch + OFF_YF1;
    float* yr1   = scratch + OFF_YR1;
    float* yf2   = scratch + OFF_YF2;
    float* yr2   = scratch + OFF_YR2;
    float* yf3   = scratch + OFF_YF3;
    float* yr3   = scratch + OFF_YR3;
    float* y3o   = scratch + OFF_Y3O;
    float* y2o   = scratch + OFF_Y2O;
    float* y1o   = scratch + OFF_Y1O;
    float* gated = scratch + OFF_GATED;
    float* Wcomb = scratch + OFF_WCOMB;
    float* bcomb = scratch + OFF_BCOMB;
    float* outp  = (float*)d_out;

    // 0) fold c1 into in-proj (exact fp32, tiled) + xd weight concat
    wprep_mm<<<dim3(16, 8), dim3(32, 8)>>>(c1_w, in_w, Wcomb);
    wprep_rest<<<512, 256>>>(in_w, in_b, c1_w, c1_b, Wcomb, bcomb);
    wcat_k<<<(80 * 256 + 255) / 256, 256>>>(xw1, xw2, wcat);

    // 1) fused in-proj + c1: [f1; z] = Wcomb @ input + bcomb  (M=512,K=512)
    tgemm_kernel<<<dim3(16, 8, BATCH), 128>>>(Wcomb, input_f, xz, bcomb,
        512, 1024, 512, 512, 1024, 512LL * 1024, 512LL * 1024, 1024, 1, 1);

    // 2) f2 = conv2s2(f1): im2col + split-K(4) GEMM (f1 inside xz)
    im2col_k<<<(BATCH * 256 * 4 * 256 + 255) / 256, 256>>>(xz, col2, 256, 32, 32,
                                                           512LL * 1024);
    biasinit_k<<<(BATCH * 256 * 256 + 255) / 256, 256>>>(f2, c2_b, 256, 256,
                                                         BATCH * 256 * 256);
    tgemm_kernel<<<dim3(4, 4, BATCH * 4), 128>>>(c2_w, col2, f2, nullptr,
        256, 256, 1024, 1024, 256, 1024LL * 256, 256LL * 256, 256, 1, 4);

    // 3) f3 = conv2s2(f2): split-K(8)
    im2col_k<<<(BATCH * 256 * 4 * 64 + 255) / 256, 256>>>(f2, col3, 256, 16, 16,
                                                          256LL * 256);
    biasinit_k<<<(BATCH * 256 * 64 + 255) / 256, 256>>>(f3, c3_b, 256, 64,
                                                        BATCH * 256 * 64);
    tgemm_kernel<<<dim3(1, 4, BATCH * 8), 128>>>(c3_w, col3, f3, nullptr,
        256, 64, 1024, 1024, 64, 1024LL * 64, 256LL * 64, 64, 1, 8);

    // 4) xd projections
    tgemm_kernel<<<dim3(16, 2, BATCH), 128>>>(wcat, xz, xd1ab, nullptr,
        80, 1024, 256, 256, 1024, 512LL * 1024, 1024LL * 80, 1, 80, 1);
    biasinit_k<<<(BATCH * 256 * 40 + 255) / 256, 256>>>(xd2, nullptr, 40, 1,
                                                        BATCH * 256 * 40);
    tgemm_kernel<<<dim3(4, 1, BATCH * 4), 128>>>(xw2, f2, xd2, nullptr,
        40, 256, 256, 256, 256, 256LL * 256, 256LL * 40, 1, 40, 4);
    biasinit_k<<<(BATCH * 64 * 40 + 255) / 256, 256>>>(xd3, nullptr, 40, 1,
                                                       BATCH * 64 * 40);
    tgemm_kernel<<<dim3(1, 1, BATCH * 4), 128>>>(xw3, f3, xd3, nullptr,
        40, 64, 256, 256, 64, 256LL * 64, 64LL * 40, 1, 40, 4);

    // 5) all six selective scans in one launch (4 lanes per (b,d))
    ScanArgs sa;
    sa.c[0] = {xz, xd1ab,      yf1, dtw1, dtb1, Al1, Dv1, L1, 0, 80, 512LL * 1024};
    sa.c[1] = {xz, xd1ab + 40, yr1, dtw2, dtb2, Al2, Dv2, L1, 1, 80, 512LL * 1024};
    sa.c[2] = {f2, xd2,        yf2, dtw2, dtb2, Al2, Dv2, L2, 0, 40, 256LL * 256};
    sa.c[3] = {f2, xd2,        yr2, dtw2, dtb2, Al2, Dv2, L2, 1, 40, 256LL * 256};
    sa.c[4] = {f3, xd3,        yf3, dtw3, dtb3, Al3, Dv3, L3, 0, 40, 256LL * 64};
    sa.c[5] = {f3, xd3,        yr3, dtw3, dtb3, Al3, Dv3, L3, 1, 40, 256LL * 64};
    scan4_kernel<<<dim3(64, 6), 128>>>(sa);

    // 6) combine (LayerNorm per direction + sum + upsample-add), bottom-up
    combine_kernel<<<BATCH * L3, 256>>>(yf3, yr3, g3, be3, g3, be3,
                                        (const float*)nullptr, y3o, L3, 8);
    combine_kernel<<<BATCH * L2, 256>>>(yf2, yr2, g2, be2, g2, be2,
                                        y3o, y2o, L2, 16);
    combine_kernel<<<BATCH * L1, 256>>>(yf1, yr1, g1, be1, g2, be2,
                                        y2o, y1o, L1, 32);

    // 7) gate with silu(z) + transpose to [b][c][p]
    gate_kernel<<<dim3(32, 8, BATCH), dim3(32, 8)>>>(y1o, xz, gated);

    // 8) out-projection straight into d_out: M=512,N=1024,K=256
    tgemm_kernel<<<dim3(16, 8, BATCH), 128>>>(out_w, gated, outp, out_b,
        512, 1024, 256, 256, 1024, 256LL * 1024, 512LL * 1024, 1024, 1, 1);
}

// round 15
// speedup vs baseline: 1.1184x; 1.0521x over previous
#include <cuda_runtime.h>
#include <math.h>
#include <stddef.h>
#include <stdint.h>

// ---------------------------------------------------------------------------
// Problem constants (fixed by the dataset)
// ---------------------------------------------------------------------------
constexpr int BATCH  = 8;
constexpr int L1 = 1024, L2 = 256, L3 = 64;

// ---------------------------------------------------------------------------
// Scratch (single __device__ buffer; no allocations anywhere)
// ---------------------------------------------------------------------------
constexpr size_t SZ_XZ    = (size_t)BATCH * 512 * 1024;
constexpr size_t SZ_F1    = (size_t)BATCH * 256 * 1024;   // spacer
constexpr size_t SZ_F2    = (size_t)BATCH * 256 * 256;
constexpr size_t SZ_F3    = (size_t)BATCH * 256 * 64;
constexpr size_t SZ_COL2  = (size_t)BATCH * 1024 * 256;
constexpr size_t SZ_COL3  = (size_t)BATCH * 1024 * 64;
constexpr size_t SZ_XD1AB = (size_t)BATCH * 1024 * 80;
constexpr size_t SZ_XD2   = (size_t)BATCH * 256 * 40;
constexpr size_t SZ_XD3   = (size_t)BATCH * 64 * 40;
constexpr size_t SZ_WCAT  = (size_t)80 * 256;
constexpr size_t SZ_Y1    = (size_t)BATCH * 1024 * 256;
constexpr size_t SZ_Y2    = (size_t)BATCH * 256 * 256;
constexpr size_t SZ_Y3    = (size_t)BATCH * 64 * 256;
constexpr size_t SZ_WCOMB = (size_t)512 * 512;
constexpr size_t SZ_BCOMB = 512;
// fragment-major weight buffers: mblks * (K/16) * 1024 floats each
constexpr size_t SZ_FM_WCOMB = (size_t)8 * 32 * 1024;   // 512x512
constexpr size_t SZ_FM_OUTW  = (size_t)8 * 16 * 1024;   // 512x256
constexpr size_t SZ_FM_C2    = (size_t)4 * 64 * 1024;   // 256x1024
constexpr size_t SZ_FM_C3    = (size_t)4 * 64 * 1024;   // 256x1024
constexpr size_t SZ_FM_WCAT  = (size_t)2 * 16 * 1024;   // 80x256 (padded)
constexpr size_t SZ_FM_XW2   = (size_t)1 * 16 * 1024;   // 40x256 (padded)
constexpr size_t SZ_FM_XW3   = (size_t)1 * 16 * 1024;   // 40x256 (padded)

constexpr size_t OFF_XZ    = 0;
constexpr size_t OFF_F1    = OFF_XZ    + SZ_XZ;
constexpr size_t OFF_F2    = OFF_F1    + SZ_F1;
constexpr size_t OFF_F3    = OFF_F2    + SZ_F2;
constexpr size_t OFF_COL2  = OFF_F3    + SZ_F3;
constexpr size_t OFF_COL3  = OFF_COL2  + SZ_COL2;
constexpr size_t OFF_XD1AB = OFF_COL3  + SZ_COL3;
constexpr size_t OFF_XD2   = OFF_XD1AB + SZ_XD1AB;
constexpr size_t OFF_XD3   = OFF_XD2   + SZ_XD2;
constexpr size_t OFF_WCAT  = OFF_XD3   + SZ_XD3;
constexpr size_t OFF_YF1   = OFF_WCAT  + SZ_WCAT;
constexpr size_t OFF_YR1   = OFF_YF1   + SZ_Y1;
constexpr size_t OFF_YF2   = OFF_YR1   + SZ_Y1;
constexpr size_t OFF_YR2   = OFF_YF2   + SZ_Y2;
constexpr size_t OFF_YF3   = OFF_YR2   + SZ_Y2;
constexpr size_t OFF_YR3   = OFF_YF3   + SZ_Y3;
constexpr size_t OFF_Y3O   = OFF_YR3   + SZ_Y3;
constexpr size_t OFF_Y2O   = OFF_Y3O   + SZ_Y3;
constexpr size_t OFF_Y1O   = OFF_Y2O   + SZ_Y2;
constexpr size_t OFF_GATED = OFF_Y1O   + SZ_Y1;
constexpr size_t OFF_WCOMB = OFF_GATED + SZ_F1;
constexpr size_t OFF_BCOMB = OFF_WCOMB + SZ_WCOMB;
constexpr size_t OFF_FM_WCOMB = OFF_BCOMB + SZ_BCOMB;
constexpr size_t OFF_FM_OUTW  = OFF_FM_WCOMB + SZ_FM_WCOMB;
constexpr size_t OFF_FM_C2    = OFF_FM_OUTW  + SZ_FM_OUTW;
constexpr size_t OFF_FM_C3    = OFF_FM_C2    + SZ_FM_C2;
constexpr size_t OFF_FM_WCAT  = OFF_FM_C3    + SZ_FM_C3;
constexpr size_t OFF_FM_XW2   = OFF_FM_WCAT  + SZ_FM_WCAT;
constexpr size_t OFF_FM_XW3   = OFF_FM_XW2   + SZ_FM_XW2;
constexpr size_t SCRATCH_TOTAL = OFF_FM_XW3 + SZ_FM_XW3;

__device__ float g_scratch[SCRATCH_TOTAL];

// ---------------------------------------------------------------------------
// tf32 helpers
// ---------------------------------------------------------------------------
__device__ __forceinline__ float f2tf(float x)
{
    uint32_t r;
    asm("cvt.rna.tf32.f32 %0, %1;" : "=r"(r) : "f"(x));
    return __uint_as_float(r);
}

__device__ __forceinline__ void mma_tf32(float* d, const uint32_t* a,
                                         const uint32_t* b)
{
    asm volatile(
        "mma.sync.aligned.m16n8k8.row.col.f32.tf32.tf32.f32 "
        "{%0,%1,%2,%3}, {%4,%5,%6,%7}, {%8,%9}, {%0,%1,%2,%3};"
        : "+f"(d[0]), "+f"(d[1]), "+f"(d[2]), "+f"(d[3])
        : "r"(a[0]), "r"(a[1]), "r"(a[2]), "r"(a[3]), "r"(b[0]), "r"(b[1]));
}

// ---------------------------------------------------------------------------
// Fragment-major weight prep.
// Afm layout: [mblk][kt][fb(8)][lane(32)][4] floats.
//   fb = s*4 + m16;  per lane (gp=lane>>2, tig=lane&3) component j:
//   rh = j&1, ch = j>>1;  m = mblk*64 + m16*16 + rh*8 + gp;
//   k = kt*16 + s*8 + ch*4 + tig;  value = f2tf(W[m][k]) (0 if m >= M).
// A warp LDG.128 at (frag base + lane*16B) is 512B coalesced.
// ---------------------------------------------------------------------------
struct PrepJob { const float* src; float* dst; int M; int K; int lda; };
struct PrepArgs { PrepJob j[7]; };

__global__ void prep_fm(PrepArgs pa)
{
    const PrepJob jb = pa.j[blockIdx.y];
    const int nkt = jb.K >> 4;
    const int mblks = (jb.M + 63) >> 6;
    const int total = mblks * nkt * 256;       // float4 count
    const int fi = blockIdx.x * 256 + threadIdx.x;
    if (fi >= total) return;
    const int lane = fi & 31;
    const int fb   = (fi >> 5) & 7;
    const int ktm  = fi >> 8;
    const int kt   = ktm % nkt;
    const int mblk = ktm / nkt;
    const int s = fb >> 2, m16 = fb & 3;
    const int gp = lane >> 2, tig = lane & 3;

    float v[4];
#pragma unroll
    for (int j = 0; j < 4; j++) {
        const int rh = j & 1, ch = j >> 1;
        const int m = mblk * 64 + m16 * 16 + rh * 8 + gp;
        const int k = kt * 16 + s * 8 + ch * 4 + tig;
        v[j] = (m < jb.M) ? f2tf(jb.src[(size_t)m * jb.lda + k]) : 0.f;
    }
    *reinterpret_cast<float4*>(jb.dst + (size_t)fi * 4) =
        make_float4(v[0], v[1], v[2], v[3]);
}

// ---------------------------------------------------------------------------
// 64x64x16 TF32 GEMM, A from fragment-major GLOBAL (no A SMEM round-trip).
// B staged in fragment-major SMEM (as R14). 128 threads / 4 warps, 32x32 warp
// tile, double-buffered (B in SMEM, A in registers).
// Contract: C[m,n] = sum_k A[m,k]*B[k,n] (+bias[m]); B batched via
// blockIdx.z = batch*ksplit + ks; C strided; ksplit>1 -> atomicAdd.
// Requires N % 64 == 0, (K/ksplit) % 16 == 0, K/ksplit >= 32.
// ---------------------------------------------------------------------------
__global__ __launch_bounds__(128)
void tgemm_fm(const float* __restrict__ Afm, const float* __restrict__ B,
              float* __restrict__ C, const float* __restrict__ bias,
              int M, int N, int K, int ldb,
              long long strideB, long long strideC,
              int ldcm, int ldcn, int ksplit)
{
    __shared__ float Bs2[2][16 * 68];

    const int tid  = threadIdx.x;
    const int lane = tid & 31;
    const int warp = tid >> 5;
    const int wm = warp & 1;
    const int wn = warp >> 1;
    const int gp  = lane >> 2;
    const int tig = lane & 3;

    const int batch  = blockIdx.z / ksplit;
    const int ks     = blockIdx.z % ksplit;
    const int nkt    = K >> 4;
    const int ktn    = nkt / ksplit;           // ktiles this block
    const int kt0    = ks * ktn;
    const int m0 = blockIdx.y * 64;
    const int n0 = blockIdx.x * 64;
    const int mblk = blockIdx.y;

    const float* Bp = B + (size_t)batch * (size_t)strideB;
    float* Cp = C + (size_t)batch * (size_t)strideC;

    // B global-load assignment
    const int brow = tid >> 3;        // 0..15 (k)
    const int bcol = (tid & 7) * 8;   // 0..56 (n)
    const float* bptr = Bp + (size_t)brow * ldb + n0 + bcol;

    // B writer fragment-major base
    const int bw_s   = brow >> 3;
    const int bw_kq  = brow & 7;
    const int bwbase = (bw_s * 8 + (tid & 7)) * 68 + (bw_kq & 3) * 2 + (bw_kq >> 2);

    // A fragment base (this thread's lane slice)
    const float* abase = Afm + ((size_t)mblk * nkt + kt0) * 1024 + lane * 4;

    float acc[2][4][4];
#pragma unroll
    for (int mt = 0; mt < 2; mt++)
#pragma unroll
        for (int nt = 0; nt < 4; nt++)
#pragma unroll
            for (int r = 0; r < 4; r++) acc[mt][nt][r] = 0.f;

    float4 ap4[2][4];     // [buf][s*2+mt]
    float bpf[8];

    // ---- prologue: tile kt0 ----
#pragma unroll
    for (int s = 0; s < 2; s++)
#pragma unroll
        for (int mt = 0; mt < 2; mt++)
            ap4[0][s * 2 + mt] = *reinterpret_cast<const float4*>(
                abase + (s * 4 + wm * 2 + mt) * 128);
    {
        const float* bp = bptr + (size_t)(kt0 * 16) * ldb;
        float4 b0 = *reinterpret_cast<const float4*>(bp);
        float4 b1 = *reinterpret_cast<const float4*>(bp + 4);
        bpf[0]=b0.x; bpf[1]=b0.y; bpf[2]=b0.z; bpf[3]=b0.w;
        bpf[4]=b1.x; bpf[5]=b1.y; bpf[6]=b1.z; bpf[7]=b1.w;
    }
#pragma unroll
    for (int i = 0; i < 8; i++)
        Bs2[0][bwbase + i * 8] = f2tf(bpf[i]);
    __syncthreads();

    int cur = 0;
    for (int it = 1; it < ktn; it++) {
        const int nxt = cur ^ 1;
        // prefetch next A fragments (registers) and B tile
        const float* ab = abase + (size_t)it * 1024;
#pragma unroll
        for (int s = 0; s < 2; s++)
#pragma unroll
            for (int mt = 0; mt < 2; mt++)
                ap4[nxt][s * 2 + mt] = *reinterpret_cast<const float4*>(
                    ab + (s * 4 + wm * 2 + mt) * 128);
        {
            const float* bp = bptr + (size_t)((kt0 + it) * 16) * ldb;
            float4 b0 = *reinterpret_cast<const float4*>(bp);
            float4 b1 = *reinterpret_cast<const float4*>(bp + 4);
            bpf[0]=b0.x; bpf[1]=b0.y; bpf[2]=b0.z; bpf[3]=b0.w;
            bpf[4]=b1.x; bpf[5]=b1.y; bpf[6]=b1.z; bpf[7]=b1.w;
        }

        // ---- mma over current buffer: 2 k8-steps ----
#pragma unroll
        for (int s = 0; s < 2; s++) {
            uint32_t af[2][4];
#pragma unroll
            for (int mt = 0; mt < 2; mt++) {
                const float4 fa = ap4[cur][s * 2 + mt];
                af[mt][0] = __float_as_uint(fa.x);
                af[mt][1] = __float_as_uint(fa.y);
                af[mt][2] = __float_as_uint(fa.z);
                af[mt][3] = __float_as_uint(fa.w);
            }
            uint32_t bf[4][2];
#pragma unroll
            for (int nt = 0; nt < 4; nt++) {
                const int boff = (s * 8 + wn * 4 + nt) * 68 + gp * 8 + tig * 2;
                const float2 fb = *reinterpret_cast<const float2*>(&Bs2[cur][boff]);
                bf[nt][0] = __float_as_uint(fb.x);
                bf[nt][1] = __float_as_uint(fb.y);
            }
#pragma unroll
            for (int mt = 0; mt < 2; mt++)
#pragma unroll
                for (int nt = 0; nt < 4; nt++)
                    mma_tf32(acc[mt][nt], af[mt], bf[nt]);
        }

        // stage prefetched B
#pragma unroll
        for (int i = 0; i < 8; i++)
            Bs2[nxt][bwbase + i * 8] = f2tf(bpf[i]);
        __syncthreads();
        cur = nxt;
    }

    // ---- final tile ----
#pragma unroll
    for (int s = 0; s < 2; s++) {
        uint32_t af[2][4];
#pragma unroll
        for (int mt = 0; mt < 2; mt++) {
            const float4 fa = ap4[cur][s * 2 + mt];
            af[mt][0] = __float_as_uint(fa.x);
            af[mt][1] = __float_as_uint(fa.y);
            af[mt][2] = __float_as_uint(fa.z);
            af[mt][3] = __float_as_uint(fa.w);
        }
        uint32_t bf[4][2];
#pragma unroll
        for (int nt = 0; nt < 4; nt++) {
            const int boff = (s * 8 + wn * 4 + nt) * 68 + gp * 8 + tig * 2;
            const float2 fb = *reinterpret_cast<const float2*>(&Bs2[cur][boff]);
            bf[nt][0] = __float_as_uint(fb.x);
            bf[nt][1] = __float_as_uint(fb.y);
        }
#pragma unroll
        for (int mt = 0; mt < 2; mt++)
#pragma unroll
            for (int nt = 0; nt < 4; nt++)
                mma_tf32(acc[mt][nt], af[mt], bf[nt]);
    }

    // ---- epilogue ----
#pragma unroll
    for (int mt = 0; mt < 2; mt++) {
        const int r0 = m0 + wm * 32 + mt * 16 + gp;
        const int r1 = r0 + 8;
#pragma unroll
        for (int nt = 0; nt < 4; nt++) {
            const int col = n0 + wn * 32 + nt * 8 + 2 * tig;
            if (ksplit == 1) {
                if (r0 < M) {
                    const float bv = bias ? bias[r0] : 0.f;
                    Cp[(size_t)r0 * ldcm + (size_t)col * ldcn]       = acc[mt][nt][0] + bv;
                    Cp[(size_t)r0 * ldcm + (size_t)(col + 1) * ldcn] = acc[mt][nt][1] + bv;
                }
                if (r1 < M) {
                    const float bv = bias ? bias[r1] : 0.f;
                    Cp[(size_t)r1 * ldcm + (size_t)col * ldcn]       = acc[mt][nt][2] + bv;
                    Cp[(size_t)r1 * ldcm + (size_t)(col + 1) * ldcn] = acc[mt][nt][3] + bv;
                }
            } else {
                if (r0 < M) {
                    atomicAdd(&Cp[(size_t)r0 * ldcm + (size_t)col * ldcn],       acc[mt][nt][0]);
                    atomicAdd(&Cp[(size_t)r0 * ldcm + (size_t)(col + 1) * ldcn], acc[mt][nt][1]);
                }
                if (r1 < M) {
                    atomicAdd(&Cp[(size_t)r1 * ldcm + (size_t)col * ldcn],       acc[mt][nt][2]);
                    atomicAdd(&Cp[(size_t)r1 * ldcm + (size_t)(col + 1) * ldcn], acc[mt][nt][3]);
                }
            }
        }
    }
}

// ---------------------------------------------------------------------------
// Wcomb rows 0..255 = c1_w @ in_w[0:256] (exact fp32, tiled)
// ---------------------------------------------------------------------------
__global__ __launch_bounds__(256)
void wprep_mm(const float* __restrict__ c1_w,
              const float* __restrict__ in_w,
              float* __restrict__ Wcomb)
{
    __shared__ float Asm[32][33];
    __shared__ float Bsm[32][33];
    const int tx = threadIdx.x;
    const int ty = threadIdx.y;
    const int n0 = blockIdx.x * 32;
    const int m0 = blockIdx.y * 32;

    float acc[4] = {0.f, 0.f, 0.f, 0.f};
    for (int k0 = 0; k0 < 256; k0 += 32) {
#pragma unroll
        for (int i = 0; i < 4; i++)
            Asm[ty + 8 * i][tx] = c1_w[(m0 + ty + 8 * i) * 256 + k0 + tx];
#pragma unroll
        for (int i = 0; i < 4; i++)
            Bsm[ty + 8 * i][tx] = in_w[(k0 + ty + 8 * i) * 512 + n0 + tx];
        __syncthreads();
#pragma unroll
        for (int kk = 0; kk < 32; kk++) {
            const float bv = Bsm[kk][tx];
#pragma unroll
            for (int i = 0; i < 4; i++)
                acc[i] += Asm[ty + 8 * i][kk] * bv;
        }
        __syncthreads();
    }
#pragma unroll
    for (int i = 0; i < 4; i++)
        Wcomb[(m0 + ty + 8 * i) * 512 + n0 + tx] = acc[i];
}

// rows 256..511 copy of in_w, combined bias bcomb, plus wcat concat
__global__ void wprep_rest(const float* __restrict__ in_w,
                           const float* __restrict__ in_b,
                           const float* __restrict__ c1_w,
                           const float* __restrict__ c1_b,
                           const float* __restrict__ xw1,
                           const float* __restrict__ xw2,
                           float* __restrict__ Wcomb,
                           float* __restrict__ bcomb,
                           float* __restrict__ wcat)
{
    const int idx = blockIdx.x * 256 + threadIdx.x;
    if (idx < 256 * 512)
        Wcomb[256 * 512 + idx] = in_w[256 * 512 + idx];
    if (idx < 80 * 256)
        wcat[idx] = (idx < 40 * 256) ? xw1[idx] : xw2[idx - 40 * 256];
    if (idx < 256) {
        float a = c1_b[idx];
#pragma unroll 4
        for (int c = 0; c < 256; c++) a += c1_w[idx * 256 + c] * in_b[c];
        bcomb[idx] = a;
    } else if (idx < 512) {
        bcomb[idx] = in_b[idx];
    }
}

// ---------------------------------------------------------------------------
// fused split-K target init: 4 regions in one launch
// ---------------------------------------------------------------------------
struct BIJob { float* C; const float* bias; int M; int N; int total; };
struct BIArgs { BIJob j[4]; };

__global__ void biasinit_all(BIArgs a)
{
    const BIJob jb = a.j[blockIdx.y];
    const int idx = blockIdx.x * 256 + threadIdx.x;
    if (idx >= jb.total) return;
    jb.C[idx] = jb.bias ? jb.bias[(idx / jb.N) % jb.M] : 0.f;
}

// ---------------------------------------------------------------------------
// im2col (compile-time pow-2 dims -> shifts, no div subroutines)
// src [B][*][Hs][Ws] (batch stride SB floats) -> dst [B][C*4][Ho*Wo]
// ---------------------------------------------------------------------------
template<int C, int Hs, int Ws, long long SB>
__global__ void im2col_t(const float* __restrict__ src, float* __restrict__ dst)
{
    constexpr int Ho = Hs / 2, Wo = Ws / 2;
    constexpr int P = Ho * Wo;
    constexpr int nTot = BATCH * C * 4 * P;
    const int idx = blockIdx.x * 256 + threadIdx.x;
    if (idx >= nTot) return;
    const int n = idx % P;
    const int k = (idx / P) % (C * 4);
    const int b = idx / (P * C * 4);
    const int c = k >> 2;
    const int i = (k >> 1) & 1;
    const int j = k & 1;
    const int h = n / Wo;
    const int w = n % Wo;
    dst[idx] = src[(size_t)b * SB + ((size_t)c * Hs + 2 * h + i) * Ws + 2 * w + j];
}

// ---------------------------------------------------------------------------
// Selective scan, 4 lanes per (b,d): lane q owns states 4q..4q+3.
// ---------------------------------------------------------------------------
struct ScanCfg {
    const float* x;
    const float* xd;
    float* y;
    const float* dtw;
    const float* dtb;
    const float* Al;
    const float* Dv;
    int L;
    int dir;
    int pitch;
    long long xbstride;
};
struct ScanArgs { ScanCfg c[6]; };

__global__ __launch_bounds__(128)
void scan4_kernel(ScanArgs args)
{
    const ScanCfg cfg = args.c[blockIdx.y];
    const int gid  = blockIdx.x * 128 + threadIdx.x;
    const int q    = gid & 3;
    const int pair = gid >> 2;
    const int b = pair >> 8;
    const int d = pair & 255;
    const int L = cfg.L;
    const int dir = cfg.dir;
    const int pitch = cfg.pitch;

    const float4 dtw0 = *reinterpret_cast<const float4*>(cfg.dtw + d * 8);
    const float4 dtw1 = *reinterpret_cast<const float4*>(cfg.dtw + d * 8 + 4);
    const float dtb_r = cfg.dtb[d];
    const float Dv_r  = cfg.Dv[d];

    float A_r[4];
    bool pwl = true;
#pragma unroll
    for (int j = 0; j < 4; j++) {
        const int n = q * 4 + j;
        A_r[j] = -expf(cfg.Al[d * 16 + n]);
        pwl = pwl && (fabsf(A_r[j] + (float)(n + 1)) <= 1e-4f * (float)(n + 1));
    }
    const bool pw = __all_sync(0xffffffffu, pwl);

    const float* xrow = cfg.x + (size_t)b * (size_t)cfg.xbstride + (size_t)d * L;
    const float* xdb  = cfg.xd + (size_t)b * L * pitch;
    float* yb = cfg.y + (size_t)b * L * 256 + d;

    float h0 = 0.f, h1 = 0.f, h2 = 0.f, h3 = 0.f;

    int l = dir ? (L - 1) : 0;
    const int step = dir ? -1 : 1;

    const float* qp = xdb + (size_t)l * pitch;
    float4 cd0 = *reinterpret_cast<const float4*>(qp);
    float4 cd1 = *reinterpret_cast<const float4*>(qp + 4);
    float4 cB  = *reinterpret_cast<const float4*>(qp + 8 + q * 4);
    float4 cC  = *reinterpret_cast<const float4*>(qp + 24 + q * 4);
    float  cxv = xrow[l];

    for (int t = 0; t < L; t++) {
        const float4 d0 = cd0, d1 = cd1, Bq = cB, Cq = cC;
        const float xv = cxv;
        const int lw = l;
        l += step;
        if (t + 1 < L) {
            const float* np = xdb + (size_t)l * pitch;
            cd0 = *reinterpret_cast<const float4*>(np);
            cd1 = *reinterpret_cast<const float4*>(np + 4);
            cB  = *reinterpret_cast<const float4*>(np + 8 + q * 4);
            cC  = *reinterpret_cast<const float4*>(np + 24 + q * 4);
            cxv = xrow[l];
        }

        float pre = dtb_r
            + d0.x * dtw0.x + d0.y * dtw0.y + d0.z * dtw0.z + d0.w * dtw0.w
            + d1.x * dtw1.x + d1.y * dtw1.y + d1.z * dtw1.z + d1.w * dtw1.w;
        const float delta = (pre > 20.f) ? pre : log1pf(__expf(pre));
        const float dx = delta * xv;

        float r0, r1, r2, r3;
        if (pw) {
            const float p1 = __expf(-delta);
            const float p2 = p1 * p1, p4 = p2 * p2;
            const float base = (q == 0) ? 1.f
                             : (q == 1) ? p4
                             : (q == 2) ? p4 * p4
                                        : p4 * p4 * p4;
            r0 = base * p1; r1 = r0 * p1; r2 = r1 * p1; r3 = r2 * p1;
        } else {
            r0 = __expf(delta * A_r[0]);
            r1 = __expf(delta * A_r[1]);
            r2 = __expf(delta * A_r[2]);
            r3 = __expf(delta * A_r[3]);
        }

        h0 = h0 * r0 + dx * Bq.x;
        h1 = h1 * r1 + dx * Bq.y;
        h2 = h2 * r2 + dx * Bq.z;
        h3 = h3 * r3 + dx * Bq.w;

        float v = h0 * Cq.x + h1 * Cq.y + h2 * Cq.z + h3 * Cq.w;
        if (q == 0) v += xv * Dv_r;
        v += __shfl_xor_sync(0xffffffffu, v, 1);
        v += __shfl_xor_sync(0xffffffffu, v, 2);
        if (q == 0) yb[(size_t)lw * 256] = v;
    }
}

// ---------------------------------------------------------------------------
// Combine: out[b,l,:] = LN(yf)*gf+bef + LN(yr)*gr+ber + up2(src)
// ---------------------------------------------------------------------------
__device__ __forceinline__ float4 warpReduce4(float4 v)
{
#pragma unroll
    for (int o = 16; o > 0; o >>= 1) {
        v.x += __shfl_xor_sync(0xffffffffu, v.x, o);
        v.y += __shfl_xor_sync(0xffffffffu, v.y, o);
        v.z += __shfl_xor_sync(0xffffffffu, v.z, o);
        v.w += __shfl_xor_sync(0xffffffffu, v.w, o);
    }
    return v;
}

__global__ __launch_bounds__(256)
void combine_kernel(const float* __restrict__ yf, const float* __restrict__ yr,
                    const float* __restrict__ gf, const float* __restrict__ bef,
                    const float* __restrict__ gr, const float* __restrict__ ber,
                    const float* __restrict__ up, float* __restrict__ out,
                    int L, int wgrid)
{
    __shared__ float4 red[8];
    const int bl = blockIdx.x;
    const int d  = threadIdx.x;
    const size_t base = (size_t)bl * 256;

    const float vf = yf[base + d];
    const float vr = yr[base + d];

    float4 s = warpReduce4(make_float4(vf, vf * vf, vr, vr * vr));
    const int warp = threadIdx.x >> 5;
    const int lane = threadIdx.x & 31;
    if (lane == 0) red[warp] = s;
    __syncthreads();
    if (warp == 0) {
        float4 t = (lane < 8) ? red[lane] : make_float4(0.f, 0.f, 0.f, 0.f);
#pragma unroll
        for (int o = 4; o > 0; o >>= 1) {
            t.x += __shfl_xor_sync(0xffffffffu, t.x, o);
            t.y += __shfl_xor_sync(0xffffffffu, t.y, o);
            t.z += __shfl_xor_sync(0xffffffffu, t.z, o);
            t.w += __shfl_xor_sync(0xffffffffu, t.w, o);
        }
        if (lane == 0) red[0] = t;
    }
    __syncthreads();
    const float4 tot = red[0];

    const float inv = 1.f / 256.f;
    const float muf = tot.x * inv;
    const float varf = tot.y * inv - muf * muf;
    const float mur = tot.z * inv;
    const float varr = tot.w * inv - mur * mur;

    const float of = (vf - muf) * rsqrtf(varf + 1e-5f) * gf[d] + bef[d];
    const float orr = (vr - mur) * rsqrtf(varr + 1e-5f) * gr[d] + ber[d];

    float u = 0.f;
    if (up) {
        const int b = bl / L, l = bl % L;
        const int hh = l / wgrid, ww = l % wgrid;
        const int lsrc = (hh >> 1) * (wgrid >> 1) + (ww >> 1);
        u = up[((size_t)b * (L >> 2) + lsrc) * 256 + d];
    }
    out[base + d] = of + orr + u;
}

// ---------------------------------------------------------------------------
// Gate: gated[b][c][p] = y1o[b][p][c] * silu(xz[b][256+c][p])
// ---------------------------------------------------------------------------
__global__ __launch_bounds__(256)
void gate_kernel(const float* __restrict__ y1o, const float* __restrict__ xz,
                 float* __restrict__ gated)
{
    __shared__ float tile[32][33];
    const int b = blockIdx.z;
    const int p0 = blockIdx.x * 32;
    const int c0 = blockIdx.y * 32;
    const int tx = threadIdx.x;
    const int ty = threadIdx.y;

#pragma unroll
    for (int k = 0; k < 4; k++) {
        const int p = p0 + ty + k * 8;
        tile[ty + k * 8][tx] = y1o[((size_t)b * 1024 + p) * 256 + c0 + tx];
    }
    __syncthreads();
#pragma unroll
    for (int k = 0; k < 4; k++) {
        const int c = c0 + ty + k * 8;
        const int p = p0 + tx;
        const float z = xz[((size_t)b * 512 + 256 + c) * 1024 + p];
        const float sz = z / (1.f + __expf(-z));
        gated[((size_t)b * 256 + c) * 1024 + p] = tile[tx][ty + k * 8] * sz;
    }
}

// ---------------------------------------------------------------------------
// Launcher
// ---------------------------------------------------------------------------
extern "C" void kernel_launch(void* const* d_in, const int* in_sizes, int n_in,
                              void* d_out, int out_size)
{
    const float* input_f = (const float*)d_in[0];
    const float* in_w    = (const float*)d_in[1];
    const float* in_b    = (const float*)d_in[2];
    const float* c1_w    = (const float*)d_in[3];
    const float* c1_b    = (const float*)d_in[4];
    const float* c2_w    = (const float*)d_in[5];
    const float* c2_b    = (const float*)d_in[6];
    const float* c3_w    = (const float*)d_in[7];
    const float* c3_b    = (const float*)d_in[8];
    const float* out_w   = (const float*)d_in[9];
    const float* out_b   = (const float*)d_in[10];
    const float* xw1  = (const float*)d_in[11];
    const float* dtw1 = (const float*)d_in[12];
    const float* dtb1 = (const float*)d_in[13];
    const float* Al1  = (const float*)d_in[14];
    const float* Dv1  = (const float*)d_in[15];
    const float* g1   = (const float*)d_in[16];
    const float* be1  = (const float*)d_in[17];
    const float* xw2  = (const float*)d_in[18];
    const float* dtw2 = (const float*)d_in[19];
    const float* dtb2 = (const float*)d_in[20];
    const float* Al2  = (const float*)d_in[21];
    const float* Dv2  = (const float*)d_in[22];
    const float* g2   = (const float*)d_in[23];
    const float* be2  = (const float*)d_in[24];
    const float* xw3  = (const float*)d_in[25];
    const float* dtw3 = (const float*)d_in[26];
    const float* dtb3 = (const float*)d_in[27];
    const float* Al3  = (const float*)d_in[28];
    const float* Dv3  = (const float*)d_in[29];
    const float* g3   = (const float*)d_in[30];
    const float* be3  = (const float*)d_in[31];
    (void)in_sizes; (void)n_in; (void)out_size;

    float* scratch = nullptr;
    cudaGetSymbolAddress((void**)&scratch, g_scratch);

    float* xz    = scratch + OFF_XZ;      // rows 0..255 = f1, 256..511 = z
    float* f2    = scratch + OFF_F2;
    float* f3    = scratch + OFF_F3;
    float* col2  = scratch + OFF_COL2;
    float* col3  = scratch + OFF_COL3;
    float* xd1ab = scratch + OFF_XD1AB;
    float* xd2   = scratch + OFF_XD2;
    float* xd3   = scratch + OFF_XD3;
    float* wcat  = scratch + OFF_WCAT;
    float* yf1   = scratch + OFF_YF1;
    float* yr1   = scratch + OFF_YR1;
    float* yf2   = scratch + OFF_YF2;
    float* yr2   = scratch + OFF_YR2;
    float* yf3   = scratch + OFF_YF3;
    float* yr3   = scratch + OFF_YR3;
    float* y3o   = scratch + OFF_Y3O;
    float* y2o   = scratch + OFF_Y2O;
    float* y1o   = scratch + OFF_Y1O;
    float* gated = scratch + OFF_GATED;
    float* Wcomb = scratch + OFF_WCOMB;
    float* bcomb = scratch + OFF_BCOMB;
    float* fmWcomb = scratch + OFF_FM_WCOMB;
    float* fmOutw  = scratch + OFF_FM_OUTW;
    float* fmC2    = scratch + OFF_FM_C2;
    float* fmC3    = scratch + OFF_FM_C3;
    float* fmWcat  = scratch + OFF_FM_WCAT;
    float* fmXw2   = scratch + OFF_FM_XW2;
    float* fmXw3   = scratch + OFF_FM_XW3;
    float* outp  = (float*)d_out;

    // 1) split-K target init (f2, f3, xd2, xd3) in one launch
    BIArgs bia;
    bia.j[0] = {f2,  c2_b,    256, 256, BATCH * 256 * 256};
    bia.j[1] = {f3,  c3_b,    256, 64,  BATCH * 256 * 64};
    bia.j[2] = {xd2, nullptr, 1,   1,   BATCH * 256 * 40};
    bia.j[3] = {xd3, nullptr, 1,   1,   BATCH * 64 * 40};
    biasinit_all<<<dim3(2048, 4), 256>>>(bia);

    // 2-3) c1-fold (exact fp32) + bias + wcat
    wprep_mm<<<dim3(16, 8), dim3(32, 8)>>>(c1_w, in_w, Wcomb);
    wprep_rest<<<512, 256>>>(in_w, in_b, c1_w, c1_b, xw1, xw2,
                             Wcomb, bcomb, wcat);

    // 4) all weights -> fragment-major tf32 (one launch, 7 jobs)
    PrepArgs pa;
    pa.j[0] = {Wcomb, fmWcomb, 512, 512,  512};
    pa.j[1] = {out_w, fmOutw,  512, 256,  256};
    pa.j[2] = {c2_w,  fmC2,    256, 1024, 1024};
    pa.j[3] = {c3_w,  fmC3,    256, 1024, 1024};
    pa.j[4] = {wcat,  fmWcat,  80,  256,  256};
    pa.j[5] = {xw2,   fmXw2,   40,  256,  256};
    pa.j[6] = {xw3,   fmXw3,   40,  256,  256};
    prep_fm<<<dim3(256, 7), 256>>>(pa);

    // 5) fused in-proj + c1: [f1; z] = Wcomb @ input + bcomb
    tgemm_fm<<<dim3(16, 8, BATCH), 128>>>(fmWcomb, input_f, xz, bcomb,
        512, 1024, 512, 1024, 512LL * 1024, 512LL * 1024, 1024, 1, 1);

    // 6-7) f2 = conv2s2(f1): im2col + split-K(4)
    im2col_t<256, 32, 32, 512LL * 1024><<<8192, 256>>>(xz, col2);
    tgemm_fm<<<dim3(4, 4, BATCH * 4), 128>>>(fmC2, col2, f2, nullptr,
        256, 256, 1024, 256, 1024LL * 256, 256LL * 256, 256, 1, 4);

    // 8-9) f3 = conv2s2(f2): split-K(8)
    im2col_t<256, 16, 16, 256LL * 256><<<2048, 256>>>(f2, col3);
    tgemm_fm<<<dim3(1, 4, BATCH * 8), 128>>>(fmC3, col3, f3, nullptr,
        256, 64, 1024, 64, 1024LL * 64, 256LL * 64, 64, 1, 8);

    // 10-12) xd projections
    tgemm_fm<<<dim3(16, 2, BATCH), 128>>>(fmWcat, xz, xd1ab, nullptr,
        80, 1024, 256, 1024, 512LL * 1024, 1024LL * 80, 1, 80, 1);
    tgemm_fm<<<dim3(4, 1, BATCH * 4), 128>>>(fmXw2, f2, xd2, nullptr,
        40, 256, 256, 256, 256LL * 256, 256LL * 40, 1, 40, 4);
    tgemm_fm<<<dim3(1, 1, BATCH * 4), 128>>>(fmXw3, f3, xd3, nullptr,
        40, 64, 256, 64, 256LL * 64, 64LL * 40, 1, 40, 4);

    // 13) all six selective scans in one launch (4 lanes per (b,d))
    ScanArgs sa;
    sa.c[0] = {xz, xd1ab,      yf1, dtw1, dtb1, Al1, Dv1, L1, 0, 80, 512LL * 1024};
    sa.c[1] = {xz, xd1ab + 40, yr1, dtw2, dtb2, Al2, Dv2, L1, 1, 80, 512LL * 1024};
    sa.c[2] = {f2, xd2,        yf2, dtw2, dtb2, Al2, Dv2, L2, 0, 40, 256LL * 256};
    sa.c[3] = {f2, xd2,        yr2, dtw2, dtb2, Al2, Dv2, L2, 1, 40, 256LL * 256};
    sa.c[4] = {f3, xd3,        yf3, dtw3, dtb3, Al3, Dv3, L3, 0, 40, 256LL * 64};
    sa.c[5] = {f3, xd3,        yr3, dtw3, dtb3, Al3, Dv3, L3, 1, 40, 256LL * 64};
    scan4_kernel<<<dim3(64, 6), 128>>>(sa);

    // 14-16) combine (LayerNorm per direction + sum + upsample-add)
    combine_kernel<<<BATCH * L3, 256>>>(yf3, yr3, g3, be3, g3, be3,
                                        (const float*)nullptr, y3o, L3, 8);
    combine_kernel<<<BATCH * L2, 256>>>(yf2, yr2, g2, be2, g2, be2,
                                        y3o, y2o, L2, 16);
    combine_kernel<<<BATCH * L1, 256>>>(yf1, yr1, g1, be1, g2, be2,
                                        y2o, y1o, L1, 32);

    // 17) gate with silu(z) + transpose to [b][c][p]
    gate_kernel<<<dim3(32, 8, BATCH), dim3(32, 8)>>>(y1o, xz, gated);

    // 18) out-projection straight into d_out
    tgemm_fm<<<dim3(16, 8, BATCH), 128>>>(fmOutw, gated, outp, out_b,
        512, 1024, 256, 1024, 256LL * 1024, 512LL * 1024, 1024, 1, 1);
}